// round 5
// baseline (speedup 1.0000x reference)
#include <cuda_runtime.h>
#include <cuda_bf16.h>
#include <math.h>
#include <cstdint>

// B=16, P=1000, N=1000, E=256, H=16, D=16, HD=256
#define BSZ   16
#define PN    1000
#define ED    256
#define MROWS (BSZ * PN)   // 16000
#define LOG2E 1.4426950408889634f

typedef unsigned long long u64;

__device__ __forceinline__ u64 dup2(float x) {
    u64 r; asm("mov.b64 %0,{%1,%1};" : "=l"(r) : "f"(x)); return r;
}
__device__ __forceinline__ void unpack2(u64 v, float& x, float& y) {
    asm("mov.b64 {%0,%1},%2;" : "=f"(x), "=f"(y) : "l"(v));
}
__device__ __forceinline__ void ffma2(u64& d, u64 a, u64 b) {
    asm("fma.rn.f32x2 %0,%1,%2,%0;" : "+l"(d) : "l"(a), "l"(b));
}
__device__ __forceinline__ u64 fadd2(u64 a, u64 b) {
    u64 r; asm("add.rn.f32x2 %0,%1,%2;" : "=l"(r) : "l"(a), "l"(b)); return r;
}
__device__ __forceinline__ float ex2f(float x) {
    float y; asm("ex2.approx.f32 %0,%1;" : "=f"(y) : "f"(x)); return y;
}
__device__ __forceinline__ float frcp(float x) {
    float y; asm("rcp.approx.f32 %0,%1;" : "=f"(y) : "f"(x)); return y;
}
__device__ __forceinline__ uint32_t smem_u32(const void* p) {
    uint32_t a;
    asm("{ .reg .u64 t; cvta.to.shared.u64 t, %1; cvt.u32.u64 %0, t; }"
        : "=r"(a) : "l"(p));
    return a;
}
__device__ __forceinline__ void ldsm4(uint32_t& r0, uint32_t& r1,
                                      uint32_t& r2, uint32_t& r3, uint32_t a) {
    asm volatile("ldmatrix.sync.aligned.m8n8.x4.shared.b16 {%0,%1,%2,%3},[%4];"
                 : "=r"(r0), "=r"(r1), "=r"(r2), "=r"(r3) : "r"(a));
}
#define MMA16816(C, A, B0, B1) \
    asm volatile("mma.sync.aligned.m16n8k16.row.col.f32.bf16.bf16.f32 " \
        "{%0,%1,%2,%3},{%4,%5,%6,%7},{%8,%9},{%0,%1,%2,%3};" \
        : "+f"((C)[0]), "+f"((C)[1]), "+f"((C)[2]), "+f"((C)[3]) \
        : "r"((A)[0]), "r"((A)[1]), "r"((A)[2]), "r"((A)[3]), \
          "r"(B0), "r"(B1))

// ---------------- scratch ----------------
__device__ float g_KV[MROWS * 512];
__device__ float g_Q[MROWS * ED];
__device__ float g_ATT[MROWS * ED];
__device__ float g_MH[MROWS * ED];
__device__ float g_WKV[ED * 512];
__device__ float g_ROWSUM[MROWS];
// split bf16 operands for tensor GEMM, padded to 1024 rows per batch
__device__ __nv_bfloat16 g_AH[16 * 1024 * 256];
__device__ __nv_bfloat16 g_AL[16 * 1024 * 256];
__device__ __nv_bfloat16 g_BH[16 * 1024 * 256];
__device__ __nv_bfloat16 g_BL[16 * 1024 * 256];

__global__ void zero_k() {
    int i = blockIdx.x * 256 + threadIdx.x;
    if (i < MROWS) g_ROWSUM[i] = 0.f;
}

__global__ void concat_wkv(const float* __restrict__ Wk, const float* __restrict__ Wv) {
    int i = blockIdx.x * 256 + threadIdx.x;
    int k = i >> 9, j = i & 511;
    g_WKV[i] = (j < 256) ? Wk[k * 256 + j] : Wv[k * 256 + (j - 256)];
}

// fp32 [16,1000,256] -> hi/lo bf16 [16,1024,256] (zero padded rows)
__global__ void split2_k(const float* __restrict__ src,
                         __nv_bfloat16* __restrict__ H, __nv_bfloat16* __restrict__ L)
{
    int i = blockIdx.x * 256 + threadIdx.x;   // 16*1024*64 float4 units
    int zr = i >> 6, c4 = i & 63;
    int z = zr >> 10, r = zr & 1023;
    float4 v = make_float4(0.f, 0.f, 0.f, 0.f);
    if (r < 1000)
        v = *(const float4*)(src + ((size_t)z * 1000 + r) * 256 + c4 * 4);
    float xs[4] = {v.x, v.y, v.z, v.w};
    ushort4 hh, ll;
    unsigned short* hp = &hh.x;
    unsigned short* lp = &ll.x;
#pragma unroll
    for (int j = 0; j < 4; ++j) {
        __nv_bfloat16 h = __float2bfloat16_rn(xs[j]);
        float res = xs[j] - __bfloat162float(h);
        __nv_bfloat16 l = __float2bfloat16_rn(res);
        hp[j] = __bfloat16_as_ushort(h);
        lp[j] = __bfloat16_as_ushort(l);
    }
    *(ushort4*)(H + (size_t)zr * 256 + c4 * 4) = hh;
    *(ushort4*)(L + (size_t)zr * 256 + c4 * 4) = ll;
}

// ---------------- scalar GEMM (modes 0,1,2 — projections) ----------------
template <int MODE>
__global__ void __launch_bounds__(256, 2)
gemm_k(const float* __restrict__ A, const float* __restrict__ Bm,
       float* __restrict__ C, int M, int N, int ldb, int ldc,
       const float* __restrict__ e1, const float* __restrict__ e2)
{
    __shared__ __align__(16) float As[2][16 * 132];
    __shared__ __align__(16) float Bs[2][16 * 132];

    const int tid = threadIdx.x;
    const int tx = tid & 15;
    const int ty = tid >> 4;
    const int m0 = blockIdx.y * 128;
    const int n0 = blockIdx.x * 128;

    const int rA = tid >> 2;
    const int cA = tid & 3;
    const int rB = tid >> 5;
    const int cB = tid & 31;

    float4 aR0, aR1, bR0, bR1;

    u64 acc2[8][4];
#pragma unroll
    for (int j = 0; j < 8; ++j)
#pragma unroll
        for (int p = 0; p < 4; ++p) acc2[j][p] = 0ULL;

#define LDA(K0) { \
    const float* ap = A + (size_t)(m0 + rA) * 256 + (K0) + cA * 4; \
    aR0 = *(const float4*)ap; \
    aR1 = *(const float4*)(ap + 64 * 256); }

#define LDB(K0) { \
    const float* bp = Bm + (size_t)((K0) + rB) * ldb + n0 + cB * 4; \
    bR0 = *(const float4*)bp; \
    bR1 = *(const float4*)(bp + 8 * ldb); }

#define STA(BUF) { \
    As[BUF][(cA*4+0)*132 + rA] = aR0.x; As[BUF][(cA*4+1)*132 + rA] = aR0.y; \
    As[BUF][(cA*4+2)*132 + rA] = aR0.z; As[BUF][(cA*4+3)*132 + rA] = aR0.w; \
    As[BUF][(cA*4+0)*132 + rA+64] = aR1.x; As[BUF][(cA*4+1)*132 + rA+64] = aR1.y; \
    As[BUF][(cA*4+2)*132 + rA+64] = aR1.z; As[BUF][(cA*4+3)*132 + rA+64] = aR1.w; }

#define STB(BUF) { \
    *(float4*)&Bs[BUF][rB * 132 + cB * 4] = bR0; \
    *(float4*)&Bs[BUF][(rB + 8) * 132 + cB * 4] = bR1; }

    LDA(0) LDB(0)
    STA(0) STB(0)
    __syncthreads();

#pragma unroll 1
    for (int t = 0; t < 16; ++t) {
        const int buf = t & 1;
        if (t < 15) { LDA((t + 1) * 16) LDB((t + 1) * 16) }
#pragma unroll
        for (int kk = 0; kk < 16; ++kk) {
            const ulonglong2* ap = (const ulonglong2*)&As[buf][kk * 132 + ty * 8];
            ulonglong2 av0 = ap[0], av1 = ap[1];
            u64 a2[4] = {av0.x, av0.y, av1.x, av1.y};
            float4 b0 = *(const float4*)&Bs[buf][kk * 132 + tx * 8];
            float4 b1 = *(const float4*)&Bs[buf][kk * 132 + tx * 8 + 4];
            u64 bd[8];
            bd[0] = dup2(b0.x); bd[1] = dup2(b0.y); bd[2] = dup2(b0.z); bd[3] = dup2(b0.w);
            bd[4] = dup2(b1.x); bd[5] = dup2(b1.y); bd[6] = dup2(b1.z); bd[7] = dup2(b1.w);
#pragma unroll
            for (int j = 0; j < 8; ++j)
#pragma unroll
                for (int p = 0; p < 4; ++p)
                    ffma2(acc2[j][p], a2[p], bd[j]);
        }
        if (t < 15) {
            STA(buf ^ 1) STB(buf ^ 1)
            __syncthreads();
        }
    }

    const int row0 = m0 + ty * 8;
    const int col0 = n0 + tx * 8;

    float ecol[8];
    if (MODE == 1) {
#pragma unroll
        for (int j = 0; j < 8; ++j) ecol[j] = e2[col0 + j];
    }
    if (MODE == 2) {
#pragma unroll
        for (int j = 0; j < 8; ++j) ecol[j] = e1[col0 + j];
    }
#pragma unroll
    for (int p = 0; p < 4; ++p) {
        float lo[8], hi[8];
#pragma unroll
        for (int j = 0; j < 8; ++j) unpack2(acc2[j][p], lo[j], hi[j]);
        int ra = row0 + 2 * p, rb = ra + 1;
        if (MODE == 1) {
            float ea = e1[ra], eb = e1[rb];
#pragma unroll
            for (int j = 0; j < 8; ++j) { lo[j] += ea * ecol[j]; hi[j] += eb * ecol[j]; }
        }
        if (MODE == 2) {
#pragma unroll
            for (int j = 0; j < 8; ++j) { lo[j] += ecol[j]; hi[j] += ecol[j]; }
        }
        *(float4*)&C[(size_t)ra * ldc + col0]     = make_float4(lo[0], lo[1], lo[2], lo[3]);
        *(float4*)&C[(size_t)ra * ldc + col0 + 4] = make_float4(lo[4], lo[5], lo[6], lo[7]);
        *(float4*)&C[(size_t)rb * ldc + col0]     = make_float4(hi[0], hi[1], hi[2], hi[3]);
        *(float4*)&C[(size_t)rb * ldc + col0 + 4] = make_float4(hi[4], hi[5], hi[6], hi[7]);
    }
#undef LDA
#undef LDB
#undef STA
#undef STB
}

// ---------------- tensor (HMMA) probe GEMM with fused clipped-softmax ----------------
// S = Ah Bh^T + Ah Bl^T + Al Bh^T ; e = exp(10*tanh(S/16)+mask); rowsum += e
// CTA 256 thr (8 warps: 4m x 2n), tile 128x128, K chunks of 64.
#define G3_PAD   72                              // bf16 row stride in smem
#define G3_TILE  (128 * G3_PAD)                  // elements per operand tile
#define G3_SMEM  (4 * G3_TILE * 2)               // bytes = 73728

__global__ void __launch_bounds__(256, 1)
gemm3_mma(const float* __restrict__ mask, float* __restrict__ out,
          float* __restrict__ rsum)
{
    extern __shared__ __align__(16) __nv_bfloat16 smb[];
    __nv_bfloat16* Ah = smb;
    __nv_bfloat16* Al = Ah + G3_TILE;
    __nv_bfloat16* Bh = Al + G3_TILE;
    __nv_bfloat16* Bl = Bh + G3_TILE;

    const int tid = threadIdx.x;
    const int lane = tid & 31;
    const int w = tid >> 5;
    const int wm = w & 3, wn = w >> 2;
    const int z = blockIdx.z, m0 = blockIdx.y * 128, n0 = blockIdx.x * 128;

    const __nv_bfloat16* pAH = g_AH + ((size_t)z * 1024 + m0) * 256;
    const __nv_bfloat16* pAL = g_AL + ((size_t)z * 1024 + m0) * 256;
    const __nv_bfloat16* pBH = g_BH + ((size_t)z * 1024 + n0) * 256;
    const __nv_bfloat16* pBL = g_BL + ((size_t)z * 1024 + n0) * 256;

    float acc[2][8][4];
#pragma unroll
    for (int mi = 0; mi < 2; ++mi)
#pragma unroll
        for (int ni = 0; ni < 8; ++ni)
#pragma unroll
            for (int q = 0; q < 4; ++q) acc[mi][ni][q] = 0.f;

    // ldmatrix lane->address components
    // A (and B) frag tiles: tile = lane>>3; A: row = (tile&1)*8 + (lane&7), kcol = (lane>>4)*8
    const int arow = ((lane >> 3) & 1) * 8 + (lane & 7);
    const int acol = (lane >> 4) * 8;
    // B x4 covers 2 n-frags: n_off = (tile>>1)*8 + (lane&7), kcol = (tile&1)*8
    const int brow = (lane >> 4) * 8 + (lane & 7);
    const int bcol = ((lane >> 3) & 1) * 8;

    const uint32_t aAH = smem_u32(Ah) + (uint32_t)(((wm * 32 + arow) * G3_PAD + acol) * 2);
    const uint32_t aAL = aAH + G3_TILE * 2;
    const uint32_t aBH = smem_u32(Bh) + (uint32_t)(((wn * 64 + brow) * G3_PAD + bcol) * 2);
    const uint32_t aBL = aBH + G3_TILE * 2;

    const int lrow = tid >> 1;               // 0..127
    const int lhalf = (tid & 1) * 32;        // 0 or 32 elements

#pragma unroll 1
    for (int kc = 0; kc < 4; ++kc) {
        __syncthreads();
        const int ko = kc * 64 + lhalf;
#pragma unroll
        for (int j = 0; j < 4; ++j) {
            *(uint4*)&Ah[lrow * G3_PAD + lhalf + j * 8] = *(const uint4*)(pAH + (size_t)lrow * 256 + ko + j * 8);
            *(uint4*)&Al[lrow * G3_PAD + lhalf + j * 8] = *(const uint4*)(pAL + (size_t)lrow * 256 + ko + j * 8);
            *(uint4*)&Bh[lrow * G3_PAD + lhalf + j * 8] = *(const uint4*)(pBH + (size_t)lrow * 256 + ko + j * 8);
            *(uint4*)&Bl[lrow * G3_PAD + lhalf + j * 8] = *(const uint4*)(pBL + (size_t)lrow * 256 + ko + j * 8);
        }
        __syncthreads();

#pragma unroll
        for (int ks = 0; ks < 4; ++ks) {
            const uint32_t koff = (uint32_t)(ks * 16 * 2);
            uint32_t aH0[4], aH1[4], aL0[4], aL1[4];
            ldsm4(aH0[0], aH0[1], aH0[2], aH0[3], aAH + koff);
            ldsm4(aH1[0], aH1[1], aH1[2], aH1[3], aAH + koff + 16 * G3_PAD * 2);
            ldsm4(aL0[0], aL0[1], aL0[2], aL0[3], aAL + koff);
            ldsm4(aL1[0], aL1[1], aL1[2], aL1[3], aAL + koff + 16 * G3_PAD * 2);
            uint32_t bH[8][2], bL[8][2];
#pragma unroll
            for (int pr = 0; pr < 4; ++pr) {
                uint32_t r0, r1, r2, r3;
                ldsm4(r0, r1, r2, r3, aBH + koff + (uint32_t)(pr * 16 * G3_PAD * 2));
                bH[2*pr][0] = r0; bH[2*pr][1] = r1;
                bH[2*pr+1][0] = r2; bH[2*pr+1][1] = r3;
                ldsm4(r0, r1, r2, r3, aBL + koff + (uint32_t)(pr * 16 * G3_PAD * 2));
                bL[2*pr][0] = r0; bL[2*pr][1] = r1;
                bL[2*pr+1][0] = r2; bL[2*pr+1][1] = r3;
            }
#pragma unroll
            for (int ni = 0; ni < 8; ++ni) {
                MMA16816(acc[0][ni], aH0, bH[ni][0], bH[ni][1]);
                MMA16816(acc[1][ni], aH1, bH[ni][0], bH[ni][1]);
                MMA16816(acc[0][ni], aH0, bL[ni][0], bL[ni][1]);
                MMA16816(acc[1][ni], aH1, bL[ni][0], bL[ni][1]);
                MMA16816(acc[0][ni], aL0, bH[ni][0], bH[ni][1]);
                MMA16816(acc[1][ni], aL1, bH[ni][0], bH[ni][1]);
            }
        }
    }

    // ---- epilogue from fragments ----
    const float* maskb = mask + (size_t)z * 1000000;
    float* outb = out + (size_t)z * 1000000;

#pragma unroll
    for (int mi = 0; mi < 2; ++mi) {
#pragma unroll
        for (int hrow = 0; hrow < 2; ++hrow) {
            int gr = m0 + wm * 32 + mi * 16 + (lane >> 2) + hrow * 8;
            bool rok = (gr < 1000);
            float rs = 0.f;
            const float* mrow = maskb + (size_t)gr * 1000;
            float* orow = outb + (size_t)gr * 1000;
#pragma unroll
            for (int ni = 0; ni < 8; ++ni) {
                int gc = n0 + wn * 64 + ni * 8 + (lane & 3) * 2;
                if (rok && gc < 1000) {
                    float v0 = acc[mi][ni][hrow * 2 + 0];
                    float v1 = acc[mi][ni][hrow * 2 + 1];
                    float2 m2 = *(const float2*)(mrow + gc);
                    float z0 = ex2f(v0 * (0.125f * LOG2E));
                    float z1 = ex2f(v1 * (0.125f * LOG2E));
                    float t0 = 10.f - 20.f * frcp(z0 + 1.f);
                    float t1 = 10.f - 20.f * frcp(z1 + 1.f);
                    float e0 = ex2f((t0 + m2.x) * LOG2E);
                    float e1 = ex2f((t1 + m2.y) * LOG2E);
                    *(float2*)(orow + gc) = make_float2(e0, e1);
                    rs += e0 + e1;
                }
            }
            rs += __shfl_xor_sync(0xFFFFFFFFu, rs, 1);
            rs += __shfl_xor_sync(0xFFFFFFFFu, rs, 2);
            if ((lane & 3) == 0 && rok)
                atomicAdd(&rsum[z * 1000 + gr], rs);
        }
    }
}

// ---------------- attention (scalar fp32x2, unchanged) ----------------
#define ATTN_SMEM_BYTES ((2048 * 2 + 128 * 132) * 4)

__global__ void __launch_bounds__(256, 2)
attn_k(const float* __restrict__ mask)
{
    extern __shared__ __align__(16) float sm[];
    float* Ks = sm;
    float* Vs = sm + 2048;
    float* Ms = sm + 4096;

    const int tid = threadIdx.x;
    const int bh = blockIdx.y;
    const int b = bh >> 4, h = bh & 15;
    const int p0 = blockIdx.x * 128;
    const int rr = tid & 63;
    const int qp = tid >> 6;
    const int pa = p0 + rr;
    const int pb = pa + 64;
    const bool oka = (pa < 1000), okb = (pb < 1000);

    u64 q2a[8], q2b[8];
    {
        const float sc = 0.25f * LOG2E;
        float qa[16], qb[16];
#pragma unroll
        for (int i = 0; i < 4; ++i) {
            float4 va = oka ? *(const float4*)(g_Q + (size_t)(b * 1000 + pa) * 256 + h * 16 + i * 4) : make_float4(0,0,0,0);
            float4 vb = okb ? *(const float4*)(g_Q + (size_t)(b * 1000 + pb) * 256 + h * 16 + i * 4) : make_float4(0,0,0,0);
            qa[i*4+0]=va.x*sc; qa[i*4+1]=va.y*sc; qa[i*4+2]=va.z*sc; qa[i*4+3]=va.w*sc;
            qb[i*4+0]=vb.x*sc; qb[i*4+1]=vb.y*sc; qb[i*4+2]=vb.z*sc; qb[i*4+3]=vb.w*sc;
        }
#pragma unroll
        for (int d = 0; d < 8; ++d) {
            u64 v; asm("mov.b64 %0,{%1,%2};" : "=l"(v) : "f"(qa[2*d]), "f"(qa[2*d+1])); q2a[d] = v;
            asm("mov.b64 %0,{%1,%2};" : "=l"(v) : "f"(qb[2*d]), "f"(qb[2*d+1])); q2b[d] = v;
        }
    }

    u64 acca[8], accb[8];
#pragma unroll
    for (int d = 0; d < 8; ++d) { acca[d] = 0ULL; accb[d] = 0ULL; }
    float dena = 0.f, denb = 0.f;

    const float* maskb = mask + (size_t)b * 1000 * 1000;
    const int w = tid >> 5, l = tid & 31;

#pragma unroll 1
    for (int nt = 0; nt < 1024; nt += 128) {
        __syncthreads();
        {
            int krow = tid >> 1, kc = (tid & 1) * 8;
            int n = nt + krow;
            float4 k0, k1, v0, v1;
            k0 = k1 = v0 = v1 = make_float4(0.f, 0.f, 0.f, 0.f);
            if (n < 1000) {
                const float* base = g_KV + (size_t)(b * 1000 + n) * 512 + h * 16 + kc;
                k0 = *(const float4*)base;       k1 = *(const float4*)(base + 4);
                v0 = *(const float4*)(base+256); v1 = *(const float4*)(base + 260);
            }
            *(float4*)&Ks[krow * 16 + kc]     = k0;
            *(float4*)&Ks[krow * 16 + kc + 4] = k1;
            *(float4*)&Vs[krow * 16 + kc]     = v0;
            *(float4*)&Vs[krow * 16 + kc + 4] = v1;
        }
#pragma unroll
        for (int it = 0; it < 16; ++it) {
            int row = w + it * 8;
            int pp = p0 + row, c0 = l * 4, nn = nt + c0;
            float4 mv;
            if (pp < 1000 && nn + 3 < 1000) {
                mv = *(const float4*)(maskb + (size_t)pp * 1000 + nn);
                mv.x *= LOG2E; mv.y *= LOG2E; mv.z *= LOG2E; mv.w *= LOG2E;
            } else {
                mv.x = (pp < 1000 && nn     < 1000) ? maskb[(size_t)pp*1000 + nn]   * LOG2E : -1e30f;
                mv.y = (pp < 1000 && nn + 1 < 1000) ? maskb[(size_t)pp*1000 + nn+1] * LOG2E : -1e30f;
                mv.z = (pp < 1000 && nn + 2 < 1000) ? maskb[(size_t)pp*1000 + nn+2] * LOG2E : -1e30f;
                mv.w = (pp < 1000 && nn + 3 < 1000) ? maskb[(size_t)pp*1000 + nn+3] * LOG2E : -1e30f;
            }
            *(float4*)&Ms[row * 132 + c0] = mv;
        }
        __syncthreads();

        const float* msa = &Ms[rr * 132 + qp * 32];
        const float* msb = msa + 64 * 132;
#pragma unroll 2
        for (int j4 = 0; j4 < 8; ++j4) {
            float4 ma4 = *(const float4*)(msa + j4 * 4);
            float4 mb4 = *(const float4*)(msb + j4 * 4);
            float mav[4] = {ma4.x, ma4.y, ma4.z, ma4.w};
            float mbv[4] = {mb4.x, mb4.y, mb4.z, mb4.w};
#pragma unroll
            for (int u = 0; u < 4; ++u) {
                const int nl = qp * 32 + j4 * 4 + u;
                const ulonglong2* kp = (const ulonglong2*)&Ks[nl * 16];
                ulonglong2 kA = kp[0], kB = kp[1], kC = kp[2], kD = kp[3];
                u64 s0 = 0ULL, s1 = 0ULL, t0 = 0ULL, t1 = 0ULL;
                ffma2(s0, q2a[0], kA.x); ffma2(s1, q2a[1], kA.y);
                ffma2(t0, q2b[0], kA.x); ffma2(t1, q2b[1], kA.y);
                ffma2(s0, q2a[2], kB.x); ffma2(s1, q2a[3], kB.y);
                ffma2(t0, q2b[2], kB.x); ffma2(t1, q2b[3], kB.y);
                ffma2(s0, q2a[4], kC.x); ffma2(s1, q2a[5], kC.y);
                ffma2(t0, q2b[4], kC.x); ffma2(t1, q2b[5], kC.y);
                ffma2(s0, q2a[6], kD.x); ffma2(s1, q2a[7], kD.y);
                ffma2(t0, q2b[6], kD.x); ffma2(t1, q2b[7], kD.y);
                u64 ss = fadd2(s0, s1), tt = fadd2(t0, t1);
                float x0, x1, y0, y1;
                unpack2(ss, x0, x1); unpack2(tt, y0, y1);
                float ea = ex2f(x0 + x1 + mav[u]);
                float eb = ex2f(y0 + y1 + mbv[u]);
                dena += ea; denb += eb;
                u64 da = dup2(ea), db = dup2(eb);
                const ulonglong2* vp = (const ulonglong2*)&Vs[nl * 16];
                ulonglong2 vA = vp[0], vB = vp[1], vC = vp[2], vD = vp[3];
                ffma2(acca[0], da, vA.x); ffma2(acca[1], da, vA.y);
                ffma2(accb[0], db, vA.x); ffma2(accb[1], db, vA.y);
                ffma2(acca[2], da, vB.x); ffma2(acca[3], da, vB.y);
                ffma2(accb[2], db, vB.x); ffma2(accb[3], db, vB.y);
                ffma2(acca[4], da, vC.x); ffma2(acca[5], da, vC.y);
                ffma2(accb[4], db, vC.x); ffma2(accb[5], db, vC.y);
                ffma2(acca[6], da, vD.x); ffma2(acca[7], da, vD.y);
                ffma2(accb[6], db, vD.x); ffma2(accb[7], db, vD.y);
            }
        }
    }

    __syncthreads();
    {
        int basea = rr * 68 + qp * 17;
        int baseb = (rr + 64) * 68 + qp * 17;
#pragma unroll
        for (int d = 0; d < 8; ++d) {
            unpack2(acca[d], Ms[basea + 2*d], Ms[basea + 2*d + 1]);
            unpack2(accb[d], Ms[baseb + 2*d], Ms[baseb + 2*d + 1]);
        }
        Ms[basea + 16] = dena;
        Ms[baseb + 16] = denb;
    }
    __syncthreads();

    if (qp == 0) {
#pragma unroll
        for (int half = 0; half < 2; ++half) {
            int p = p0 + rr + half * 64;
            if (p < 1000) {
                int rbase = (rr + half * 64) * 68;
                float tot[16];
#pragma unroll
                for (int d = 0; d < 16; ++d) tot[d] = 0.f;
                float dt = 0.f;
#pragma unroll
                for (int g = 0; g < 4; ++g) {
                    const float* rp = &Ms[rbase + g * 17];
                    dt += rp[16];
#pragma unroll
                    for (int d = 0; d < 16; ++d) tot[d] += rp[d];
                }
                float inv = 1.f / dt;
                float* op = g_ATT + (size_t)(b * 1000 + p) * 256 + h * 16;
#pragma unroll
                for (int d = 0; d < 16; ++d) op[d] = tot[d] * inv;
            }
        }
    }
}

// ---------------- normalize ----------------
__global__ void norm_k(float* __restrict__ out) {
    int row = blockIdx.x;
    int c = threadIdx.x;
    if (c < 250) {
        float inv = 1.0f / g_ROWSUM[row];
        float4* p = (float4*)(out + (size_t)row * 1000);
        float4 v = p[c];
        v.x *= inv; v.y *= inv; v.z *= inv; v.w *= inv;
        p[c] = v;
    }
}

// ---------------- launch ----------------
extern "C" void kernel_launch(void* const* d_in, const int* in_sizes, int n_in,
                              void* d_out, int out_size)
{
    const float* last  = (const float*)d_in[0];
    const float* attr  = (const float*)d_in[1];
    const float* mask  = (const float*)d_in[2];
    const float* nodes = (const float*)d_in[3];
    const float* Wq    = (const float*)d_in[4];
    const float* Wk    = (const float*)d_in[5];
    const float* Wv    = (const float*)d_in[6];
    const float* Wc    = (const float*)d_in[7];
    const float* bc    = (const float*)d_in[8];
    float* out = (float*)d_out;

    void* p;
    cudaGetSymbolAddress(&p, g_KV);     float* gKV  = (float*)p;
    cudaGetSymbolAddress(&p, g_Q);      float* gQ   = (float*)p;
    cudaGetSymbolAddress(&p, g_ATT);    float* gATT = (float*)p;
    cudaGetSymbolAddress(&p, g_MH);     float* gMH  = (float*)p;
    cudaGetSymbolAddress(&p, g_WKV);    float* gWKV = (float*)p;
    cudaGetSymbolAddress(&p, g_ROWSUM); float* gRS  = (float*)p;
    cudaGetSymbolAddress(&p, g_AH);     __nv_bfloat16* gAH = (__nv_bfloat16*)p;
    cudaGetSymbolAddress(&p, g_AL);     __nv_bfloat16* gAL = (__nv_bfloat16*)p;
    cudaGetSymbolAddress(&p, g_BH);     __nv_bfloat16* gBH = (__nv_bfloat16*)p;
    cudaGetSymbolAddress(&p, g_BL);     __nv_bfloat16* gBL = (__nv_bfloat16*)p;

    cudaFuncSetAttribute(attn_k, cudaFuncAttributeMaxDynamicSharedMemorySize,
                         ATTN_SMEM_BYTES);
    cudaFuncSetAttribute(gemm3_mma, cudaFuncAttributeMaxDynamicSharedMemorySize,
                         G3_SMEM);

    zero_k<<<(MROWS + 255) / 256, 256>>>();
    concat_wkv<<<512, 256>>>(Wk, Wv);
    // split nodes (B operand) early — independent of the pipeline
    split2_k<<<4096, 256>>>(nodes, gBH, gBL);

    gemm_k<0><<<dim3(4, 125), 256>>>(nodes, gWKV, gKV, MROWS, 512, 512, 512,
                                     nullptr, nullptr);
    gemm_k<1><<<dim3(2, 125), 256>>>(last, Wq, gQ, MROWS, 256, 256, 256,
                                     attr, Wq + 256 * 256);

    attn_k<<<dim3(8, 256), 256, ATTN_SMEM_BYTES>>>(mask);

    gemm_k<2><<<dim3(2, 125), 256>>>(gATT, Wc, gMH, MROWS, 256, 256, 256,
                                     bc, nullptr);

    // split mh (A operand), then tensor-core probe GEMM + clipped-softmax epilogue
    split2_k<<<4096, 256>>>(gMH, gAH, gAL);
    gemm3_mma<<<dim3(8, 8, 16), 256, G3_SMEM>>>(mask, out, gRS);

    norm_k<<<MROWS, 256>>>(out);
}

// round 6
// speedup vs baseline: 1.6558x; 1.6558x over previous
#include <cuda_runtime.h>
#include <cuda_bf16.h>
#include <math.h>
#include <cstdint>

// B=16, P=1000, N=1000, E=256, H=16, D=16, HD=256
#define BSZ   16
#define PN    1000
#define ED    256
#define MROWS (BSZ * PN)   // 16000
#define LOG2E 1.4426950408889634f

typedef unsigned long long u64;

__device__ __forceinline__ u64 dup2(float x) {
    u64 r; asm("mov.b64 %0,{%1,%1};" : "=l"(r) : "f"(x)); return r;
}
__device__ __forceinline__ void unpack2(u64 v, float& x, float& y) {
    asm("mov.b64 {%0,%1},%2;" : "=f"(x), "=f"(y) : "l"(v));
}
__device__ __forceinline__ void ffma2(u64& d, u64 a, u64 b) {
    asm("fma.rn.f32x2 %0,%1,%2,%0;" : "+l"(d) : "l"(a), "l"(b));
}
__device__ __forceinline__ float ex2f(float x) {
    float y; asm("ex2.approx.f32 %0,%1;" : "=f"(y) : "f"(x)); return y;
}
__device__ __forceinline__ float frcp(float x) {
    float y; asm("rcp.approx.f32 %0,%1;" : "=f"(y) : "f"(x)); return y;
}
__device__ __forceinline__ uint32_t smem_u32(const void* p) {
    uint32_t a;
    asm("{ .reg .u64 t; cvta.to.shared.u64 t, %1; cvt.u32.u64 %0, t; }"
        : "=r"(a) : "l"(p));
    return a;
}
__device__ __forceinline__ void ldsm4(uint32_t& r0, uint32_t& r1,
                                      uint32_t& r2, uint32_t& r3, uint32_t a) {
    asm volatile("ldmatrix.sync.aligned.m8n8.x4.shared.b16 {%0,%1,%2,%3},[%4];"
                 : "=r"(r0), "=r"(r1), "=r"(r2), "=r"(r3) : "r"(a));
}
__device__ __forceinline__ void ldsm4t(uint32_t& r0, uint32_t& r1,
                                       uint32_t& r2, uint32_t& r3, uint32_t a) {
    asm volatile("ldmatrix.sync.aligned.m8n8.x4.trans.shared.b16 {%0,%1,%2,%3},[%4];"
                 : "=r"(r0), "=r"(r1), "=r"(r2), "=r"(r3) : "r"(a));
}
__device__ __forceinline__ uint32_t packbf(float hi, float lo) {
    uint32_t r; asm("cvt.rn.bf16x2.f32 %0,%1,%2;" : "=r"(r) : "f"(hi), "f"(lo));
    return r;
}
#define MMA16816(C, A, B0, B1) \
    asm volatile("mma.sync.aligned.m16n8k16.row.col.f32.bf16.bf16.f32 " \
        "{%0,%1,%2,%3},{%4,%5,%6,%7},{%8,%9},{%0,%1,%2,%3};" \
        : "+f"((C)[0]), "+f"((C)[1]), "+f"((C)[2]), "+f"((C)[3]) \
        : "r"((A)[0]), "r"((A)[1]), "r"((A)[2]), "r"((A)[3]), \
          "r"(B0), "r"(B1))
#define CP_COMMIT() asm volatile("cp.async.commit_group;" ::: "memory")
#define CP_WAIT1()  asm volatile("cp.async.wait_group 1;" ::: "memory")
#define CP_WAIT0()  asm volatile("cp.async.wait_group 0;" ::: "memory")

// ---------------- scratch ----------------
__device__ float g_KV[MROWS * 512];
__device__ float g_Q[MROWS * ED];
__device__ float g_ATT[MROWS * ED];
__device__ float g_MH[MROWS * ED];
__device__ float g_WKV[ED * 512];
__device__ float g_ROWSUM[MROWS];
__device__ __nv_bfloat16 g_AH[16 * 1024 * 256];
__device__ __nv_bfloat16 g_AL[16 * 1024 * 256];
__device__ __nv_bfloat16 g_BH[16 * 1024 * 256];
__device__ __nv_bfloat16 g_BL[16 * 1024 * 256];
__device__ __nv_bfloat16 g_QH[16 * 1024 * 256];
__device__ __nv_bfloat16 g_QL[16 * 1024 * 256];
__device__ __nv_bfloat16 g_KVH[16 * 1024 * 512];
__device__ __nv_bfloat16 g_KVL[16 * 1024 * 512];

__global__ void zero_k() {
    int i = blockIdx.x * 256 + threadIdx.x;
    if (i < MROWS) g_ROWSUM[i] = 0.f;
}

__global__ void concat_wkv(const float* __restrict__ Wk, const float* __restrict__ Wv) {
    int i = blockIdx.x * 256 + threadIdx.x;
    int k = i >> 9, j = i & 511;
    g_WKV[i] = (j < 256) ? Wk[k * 256 + j] : Wv[k * 256 + (j - 256)];
}

// fp32 [16,1000,cols] -> scaled hi/lo bf16 [16,1024,cols] (zero-padded rows)
__global__ void splitg_k(const float* __restrict__ src,
                         __nv_bfloat16* __restrict__ H, __nv_bfloat16* __restrict__ L,
                         int c4shift, float scale)
{
    int i = blockIdx.x * 256 + threadIdx.x;
    int c4 = i & ((1 << c4shift) - 1);
    int zr = i >> c4shift;
    int z = zr >> 10, r = zr & 1023;
    int cols = 4 << c4shift;
    float4 v = make_float4(0.f, 0.f, 0.f, 0.f);
    if (r < 1000)
        v = *(const float4*)(src + ((size_t)z * 1000 + r) * cols + c4 * 4);
    float xs[4] = {v.x * scale, v.y * scale, v.z * scale, v.w * scale};
    ushort4 hh, ll;
    unsigned short* hp = &hh.x;
    unsigned short* lp = &ll.x;
#pragma unroll
    for (int j = 0; j < 4; ++j) {
        __nv_bfloat16 h = __float2bfloat16_rn(xs[j]);
        float res = xs[j] - __bfloat162float(h);
        __nv_bfloat16 l = __float2bfloat16_rn(res);
        hp[j] = __bfloat16_as_ushort(h);
        lp[j] = __bfloat16_as_ushort(l);
    }
    *(ushort4*)(H + (size_t)zr * cols + c4 * 4) = hh;
    *(ushort4*)(L + (size_t)zr * cols + c4 * 4) = ll;
}

// ---------------- scalar GEMM (modes 0,1,2 — projections) ----------------
template <int MODE>
__global__ void __launch_bounds__(256, 2)
gemm_k(const float* __restrict__ A, const float* __restrict__ Bm,
       float* __restrict__ C, int M, int N, int ldb, int ldc,
       const float* __restrict__ e1, const float* __restrict__ e2)
{
    __shared__ __align__(16) float As[2][16 * 132];
    __shared__ __align__(16) float Bs[2][16 * 132];

    const int tid = threadIdx.x;
    const int tx = tid & 15;
    const int ty = tid >> 4;
    const int m0 = blockIdx.y * 128;
    const int n0 = blockIdx.x * 128;

    const int rA = tid >> 2;
    const int cA = tid & 3;
    const int rB = tid >> 5;
    const int cB = tid & 31;

    float4 aR0, aR1, bR0, bR1;

    u64 acc2[8][4];
#pragma unroll
    for (int j = 0; j < 8; ++j)
#pragma unroll
        for (int p = 0; p < 4; ++p) acc2[j][p] = 0ULL;

#define LDA(K0) { \
    const float* ap = A + (size_t)(m0 + rA) * 256 + (K0) + cA * 4; \
    aR0 = *(const float4*)ap; \
    aR1 = *(const float4*)(ap + 64 * 256); }

#define LDB(K0) { \
    const float* bp = Bm + (size_t)((K0) + rB) * ldb + n0 + cB * 4; \
    bR0 = *(const float4*)bp; \
    bR1 = *(const float4*)(bp + 8 * ldb); }

#define STA(BUF) { \
    As[BUF][(cA*4+0)*132 + rA] = aR0.x; As[BUF][(cA*4+1)*132 + rA] = aR0.y; \
    As[BUF][(cA*4+2)*132 + rA] = aR0.z; As[BUF][(cA*4+3)*132 + rA] = aR0.w; \
    As[BUF][(cA*4+0)*132 + rA+64] = aR1.x; As[BUF][(cA*4+1)*132 + rA+64] = aR1.y; \
    As[BUF][(cA*4+2)*132 + rA+64] = aR1.z; As[BUF][(cA*4+3)*132 + rA+64] = aR1.w; }

#define STB(BUF) { \
    *(float4*)&Bs[BUF][rB * 132 + cB * 4] = bR0; \
    *(float4*)&Bs[BUF][(rB + 8) * 132 + cB * 4] = bR1; }

    LDA(0) LDB(0)
    STA(0) STB(0)
    __syncthreads();

#pragma unroll 1
    for (int t = 0; t < 16; ++t) {
        const int buf = t & 1;
        if (t < 15) { LDA((t + 1) * 16) LDB((t + 1) * 16) }
#pragma unroll
        for (int kk = 0; kk < 16; ++kk) {
            const ulonglong2* ap = (const ulonglong2*)&As[buf][kk * 132 + ty * 8];
            ulonglong2 av0 = ap[0], av1 = ap[1];
            u64 a2[4] = {av0.x, av0.y, av1.x, av1.y};
            float4 b0 = *(const float4*)&Bs[buf][kk * 132 + tx * 8];
            float4 b1 = *(const float4*)&Bs[buf][kk * 132 + tx * 8 + 4];
            u64 bd[8];
            bd[0] = dup2(b0.x); bd[1] = dup2(b0.y); bd[2] = dup2(b0.z); bd[3] = dup2(b0.w);
            bd[4] = dup2(b1.x); bd[5] = dup2(b1.y); bd[6] = dup2(b1.z); bd[7] = dup2(b1.w);
#pragma unroll
            for (int j = 0; j < 8; ++j)
#pragma unroll
                for (int p = 0; p < 4; ++p)
                    ffma2(acc2[j][p], a2[p], bd[j]);
        }
        if (t < 15) {
            STA(buf ^ 1) STB(buf ^ 1)
            __syncthreads();
        }
    }

    const int row0 = m0 + ty * 8;
    const int col0 = n0 + tx * 8;

    float ecol[8];
    if (MODE == 1) {
#pragma unroll
        for (int j = 0; j < 8; ++j) ecol[j] = e2[col0 + j];
    }
    if (MODE == 2) {
#pragma unroll
        for (int j = 0; j < 8; ++j) ecol[j] = e1[col0 + j];
    }
#pragma unroll
    for (int p = 0; p < 4; ++p) {
        float lo[8], hi[8];
#pragma unroll
        for (int j = 0; j < 8; ++j) unpack2(acc2[j][p], lo[j], hi[j]);
        int ra = row0 + 2 * p, rb = ra + 1;
        if (MODE == 1) {
            float ea = e1[ra], eb = e1[rb];
#pragma unroll
            for (int j = 0; j < 8; ++j) { lo[j] += ea * ecol[j]; hi[j] += eb * ecol[j]; }
        }
        if (MODE == 2) {
#pragma unroll
            for (int j = 0; j < 8; ++j) { lo[j] += ecol[j]; hi[j] += ecol[j]; }
        }
        *(float4*)&C[(size_t)ra * ldc + col0]     = make_float4(lo[0], lo[1], lo[2], lo[3]);
        *(float4*)&C[(size_t)ra * ldc + col0 + 4] = make_float4(lo[4], lo[5], lo[6], lo[7]);
        *(float4*)&C[(size_t)rb * ldc + col0]     = make_float4(hi[0], hi[1], hi[2], hi[3]);
        *(float4*)&C[(size_t)rb * ldc + col0 + 4] = make_float4(hi[4], hi[5], hi[6], hi[7]);
    }
#undef LDA
#undef LDB
#undef STA
#undef STB
}

// ---------------- tensor (HMMA) probe GEMM with fused clipped-softmax ----------------
#define G3_PAD   72
#define G3_TILE  (128 * G3_PAD)
#define G3_SMEM  (4 * G3_TILE * 2)

__global__ void __launch_bounds__(256, 1)
gemm3_mma(const float* __restrict__ mask, float* __restrict__ out,
          float* __restrict__ rsum)
{
    extern __shared__ __align__(16) __nv_bfloat16 smb[];
    __nv_bfloat16* Ah = smb;
    __nv_bfloat16* Al = Ah + G3_TILE;
    __nv_bfloat16* Bh = Al + G3_TILE;
    __nv_bfloat16* Bl = Bh + G3_TILE;

    const int tid = threadIdx.x;
    const int lane = tid & 31;
    const int w = tid >> 5;
    const int wm = w & 3, wn = w >> 2;
    const int z = blockIdx.z, m0 = blockIdx.y * 128, n0 = blockIdx.x * 128;

    const __nv_bfloat16* pAH = g_AH + ((size_t)z * 1024 + m0) * 256;
    const __nv_bfloat16* pAL = g_AL + ((size_t)z * 1024 + m0) * 256;
    const __nv_bfloat16* pBH = g_BH + ((size_t)z * 1024 + n0) * 256;
    const __nv_bfloat16* pBL = g_BL + ((size_t)z * 1024 + n0) * 256;

    float acc[2][8][4];
#pragma unroll
    for (int mi = 0; mi < 2; ++mi)
#pragma unroll
        for (int ni = 0; ni < 8; ++ni)
#pragma unroll
            for (int q = 0; q < 4; ++q) acc[mi][ni][q] = 0.f;

    const int arow = ((lane >> 3) & 1) * 8 + (lane & 7);
    const int acol = (lane >> 4) * 8;
    const int brow = (lane >> 4) * 8 + (lane & 7);
    const int bcol = ((lane >> 3) & 1) * 8;

    const uint32_t aAH = smem_u32(Ah) + (uint32_t)(((wm * 32 + arow) * G3_PAD + acol) * 2);
    const uint32_t aAL = aAH + G3_TILE * 2;
    const uint32_t aBH = smem_u32(Bh) + (uint32_t)(((wn * 64 + brow) * G3_PAD + bcol) * 2);
    const uint32_t aBL = aBH + G3_TILE * 2;

    const int lrow = tid >> 1;
    const int lhalf = (tid & 1) * 32;

#pragma unroll 1
    for (int kc = 0; kc < 4; ++kc) {
        __syncthreads();
        const int ko = kc * 64 + lhalf;
#pragma unroll
        for (int j = 0; j < 4; ++j) {
            *(uint4*)&Ah[lrow * G3_PAD + lhalf + j * 8] = *(const uint4*)(pAH + (size_t)lrow * 256 + ko + j * 8);
            *(uint4*)&Al[lrow * G3_PAD + lhalf + j * 8] = *(const uint4*)(pAL + (size_t)lrow * 256 + ko + j * 8);
            *(uint4*)&Bh[lrow * G3_PAD + lhalf + j * 8] = *(const uint4*)(pBH + (size_t)lrow * 256 + ko + j * 8);
            *(uint4*)&Bl[lrow * G3_PAD + lhalf + j * 8] = *(const uint4*)(pBL + (size_t)lrow * 256 + ko + j * 8);
        }
        __syncthreads();

#pragma unroll
        for (int ks = 0; ks < 4; ++ks) {
            const uint32_t koff = (uint32_t)(ks * 16 * 2);
            uint32_t aH0[4], aH1[4], aL0[4], aL1[4];
            ldsm4(aH0[0], aH0[1], aH0[2], aH0[3], aAH + koff);
            ldsm4(aH1[0], aH1[1], aH1[2], aH1[3], aAH + koff + 16 * G3_PAD * 2);
            ldsm4(aL0[0], aL0[1], aL0[2], aL0[3], aAL + koff);
            ldsm4(aL1[0], aL1[1], aL1[2], aL1[3], aAL + koff + 16 * G3_PAD * 2);
            uint32_t bH[8][2], bL[8][2];
#pragma unroll
            for (int pr = 0; pr < 4; ++pr) {
                uint32_t r0, r1, r2, r3;
                ldsm4(r0, r1, r2, r3, aBH + koff + (uint32_t)(pr * 16 * G3_PAD * 2));
                bH[2*pr][0] = r0; bH[2*pr][1] = r1;
                bH[2*pr+1][0] = r2; bH[2*pr+1][1] = r3;
                ldsm4(r0, r1, r2, r3, aBL + koff + (uint32_t)(pr * 16 * G3_PAD * 2));
                bL[2*pr][0] = r0; bL[2*pr][1] = r1;
                bL[2*pr+1][0] = r2; bL[2*pr+1][1] = r3;
            }
#pragma unroll
            for (int ni = 0; ni < 8; ++ni) {
                MMA16816(acc[0][ni], aH0, bH[ni][0], bH[ni][1]);
                MMA16816(acc[1][ni], aH1, bH[ni][0], bH[ni][1]);
                MMA16816(acc[0][ni], aH0, bL[ni][0], bL[ni][1]);
                MMA16816(acc[1][ni], aH1, bL[ni][0], bL[ni][1]);
                MMA16816(acc[0][ni], aL0, bH[ni][0], bH[ni][1]);
                MMA16816(acc[1][ni], aL1, bH[ni][0], bH[ni][1]);
            }
        }
    }

    const float* maskb = mask + (size_t)z * 1000000;
    float* outb = out + (size_t)z * 1000000;

#pragma unroll
    for (int mi = 0; mi < 2; ++mi) {
#pragma unroll
        for (int hrow = 0; hrow < 2; ++hrow) {
            int gr = m0 + wm * 32 + mi * 16 + (lane >> 2) + hrow * 8;
            bool rok = (gr < 1000);
            float rs = 0.f;
            const float* mrow = maskb + (size_t)gr * 1000;
            float* orow = outb + (size_t)gr * 1000;
#pragma unroll
            for (int ni = 0; ni < 8; ++ni) {
                int gc = n0 + wn * 64 + ni * 8 + (lane & 3) * 2;
                if (rok && gc < 1000) {
                    float v0 = acc[mi][ni][hrow * 2 + 0];
                    float v1 = acc[mi][ni][hrow * 2 + 1];
                    float2 m2 = *(const float2*)(mrow + gc);
                    float z0 = ex2f(v0 * (0.125f * LOG2E));
                    float z1 = ex2f(v1 * (0.125f * LOG2E));
                    float t0 = 10.f - 20.f * frcp(z0 + 1.f);
                    float t1 = 10.f - 20.f * frcp(z1 + 1.f);
                    float e0 = ex2f((t0 + m2.x) * LOG2E);
                    float e1 = ex2f((t1 + m2.y) * LOG2E);
                    *(float2*)(orow + gc) = make_float2(e0, e1);
                    rs += e0 + e1;
                }
            }
            rs += __shfl_xor_sync(0xFFFFFFFFu, rs, 1);
            rs += __shfl_xor_sync(0xFFFFFFFFu, rs, 2);
            if ((lane & 3) == 0 && rok)
                atomicAdd(&rsum[z * 1000 + gr], rs);
        }
    }
}

// ---------------- HMMA flash attention ----------------
// CTA = (p-tile 128, head-group 4, batch). 8 warps x 16 p-rows.
// smem: QH/QL [128][72], per-buffer: KH/KL/VH/VL [64][72] + mask [128][68] f32, x2 buffers
#define AT_BUFSZ 71680
#define AT_SMEM  (36864 + 2 * AT_BUFSZ)   // 180224

__global__ void __launch_bounds__(256, 1)
attn_mma(const float* __restrict__ mask)
{
    extern __shared__ __align__(16) char atsm[];
    const uint32_t sb = smem_u32(atsm);
    const int tid = threadIdx.x, lane = tid & 31, w = tid >> 5;
    const int p0 = blockIdx.x * 128;
    const int hg = blockIdx.y;
    const int b  = blockIdx.z;

    const __nv_bfloat16* gQHp = g_QH + ((size_t)b * 1024 + p0) * 256 + hg * 64;
    const __nv_bfloat16* gQLp = g_QL + ((size_t)b * 1024 + p0) * 256 + hg * 64;
    const __nv_bfloat16* gKVH = g_KVH + (size_t)b * 1024 * 512;
    const __nv_bfloat16* gKVL = g_KVL + (size_t)b * 1024 * 512;
    const float* gM = mask + (size_t)b * 1000000;

    auto cpa = [](uint32_t dst, const void* src, int n) {
        asm volatile("cp.async.cg.shared.global [%0],[%1],16,%2;"
                     :: "r"(dst), "l"(src), "r"(n) : "memory");
    };

    auto issue_tile = [&](int nt, int buf) {
        const int n0 = nt * 64;
        const uint32_t base = sb + 36864u + (uint32_t)buf * AT_BUFSZ;
#pragma unroll
        for (int i = 0; i < 2; ++i) {
            int idx = i * 256 + tid, row = idx >> 3, c = idx & 7;
            size_t srow = (size_t)(b * 1024 + n0 + row) * 512;
            uint32_t doff = (uint32_t)((row * 72 + c * 8) * 2);
            cpa(base + doff,          gKVH - (size_t)b*1024*512 + srow + hg*64 + c*8, 16);
            cpa(base + 9216 + doff,   gKVL - (size_t)b*1024*512 + srow + hg*64 + c*8, 16);
            cpa(base + 18432 + doff,  gKVH - (size_t)b*1024*512 + srow + 256 + hg*64 + c*8, 16);
            cpa(base + 27648 + doff,  gKVL - (size_t)b*1024*512 + srow + 256 + hg*64 + c*8, 16);
        }
#pragma unroll
        for (int i = 0; i < 8; ++i) {
            int idx = i * 256 + tid, row = idx >> 4, c = idx & 15;
            int gr = p0 + row, gc = n0 + c * 4;
            bool ok = (gr < 1000) && (gc < 1000);
            const float* src = ok ? (gM + (size_t)gr * 1000 + gc) : gM;
            cpa(base + 36864u + (uint32_t)((row * 68 + c * 4) * 4), src, ok ? 16 : 0);
        }
    };

    // prologue: Q + tile0 (group 0), tile1 (group 1)
#pragma unroll
    for (int i = 0; i < 4; ++i) {
        int idx = i * 256 + tid, row = idx >> 3, c = idx & 7;
        uint32_t doff = (uint32_t)((row * 72 + c * 8) * 2);
        cpa(sb + doff,          gQHp + (size_t)row * 256 + c * 8, 16);
        cpa(sb + 18432 + doff,  gQLp + (size_t)row * 256 + c * 8, 16);
    }
    issue_tile(0, 0);
    CP_COMMIT();
    issue_tile(1, 1);
    CP_COMMIT();

    // lane address components (validated layouts from gemm3_mma)
    const int qrow = w * 16 + (lane & 7) + ((lane >> 3) & 1) * 8;
    const int qcol = ((lane >> 4) & 1) * 8;
    const int krow = (lane & 7) + ((lane >> 4) & 1) * 8;
    const int kcol = ((lane >> 3) & 1) * 8;
    const int vrow = (lane & 7) + ((lane >> 3) & 1) * 8;
    const int vcol = ((lane >> 4) & 1) * 8;

    uint32_t qh[4][4], ql[4][4];
    float out[4][2][4];
    float denA[4], denB[4];
#pragma unroll
    for (int h = 0; h < 4; ++h) {
        denA[h] = 0.f; denB[h] = 0.f;
#pragma unroll
        for (int d = 0; d < 2; ++d)
#pragma unroll
            for (int q = 0; q < 4; ++q) out[h][d][q] = 0.f;
    }

#pragma unroll 1
    for (int nt = 0; nt < 16; ++nt) {
        if (nt < 15) { CP_WAIT1(); } else { CP_WAIT0(); }
        __syncthreads();

        const uint32_t bufb = sb + 36864u + (uint32_t)(nt & 1) * AT_BUFSZ;
        const uint32_t aM = bufb + 36864u;

        if (nt == 0) {
            const uint32_t aQ = sb + (uint32_t)((qrow * 72 + qcol) * 2);
#pragma unroll
            for (int h = 0; h < 4; ++h) {
                ldsm4(qh[h][0], qh[h][1], qh[h][2], qh[h][3], aQ + (uint32_t)(h * 32));
                ldsm4(ql[h][0], ql[h][1], ql[h][2], ql[h][3], aQ + 18432u + (uint32_t)(h * 32));
            }
        }
        if (nt == 15) {
            // patch mask cols n >= 1000 (n0=960: cols 40..63) with -1e30
            for (int i = tid; i < 3072; i += 256) {
                int row = i / 24, c = 40 + (i - row * 24);
                asm volatile("st.shared.f32 [%0],%1;"
                             :: "r"(aM + (uint32_t)((row * 68 + c) * 4)), "f"(-1e30f));
            }
            __syncthreads();
        }

        // mask regs (shared across heads)
        float mk[8][4];
        {
            uint32_t ab = aM + (uint32_t)((((w * 16) + (lane >> 2)) * 68 + (lane & 3) * 2) * 4);
#pragma unroll
            for (int j = 0; j < 8; ++j) {
                asm volatile("ld.shared.v2.f32 {%0,%1},[%2];"
                             : "=f"(mk[j][0]), "=f"(mk[j][1]) : "r"(ab + (uint32_t)(j * 32)));
                asm volatile("ld.shared.v2.f32 {%0,%1},[%2];"
                             : "=f"(mk[j][2]), "=f"(mk[j][3]) : "r"(ab + (uint32_t)(j * 32 + 2176)));
            }
        }

#pragma unroll
        for (int h = 0; h < 4; ++h) {
            const uint32_t aK = bufb + (uint32_t)(((krow) * 72 + h * 16 + kcol) * 2);
            uint32_t kh[8][2], kl[8][2];
#pragma unroll
            for (int jj = 0; jj < 4; ++jj) {
                ldsm4(kh[2*jj][0], kh[2*jj][1], kh[2*jj+1][0], kh[2*jj+1][1],
                      aK + (uint32_t)(jj * 2304));
                ldsm4(kl[2*jj][0], kl[2*jj][1], kl[2*jj+1][0], kl[2*jj+1][1],
                      aK + 9216u + (uint32_t)(jj * 2304));
            }
            float S[8][4];
#pragma unroll
            for (int j = 0; j < 8; ++j) {
                S[j][0] = 0.f; S[j][1] = 0.f; S[j][2] = 0.f; S[j][3] = 0.f;
                MMA16816(S[j], qh[h], kh[j][0], kh[j][1]);
                MMA16816(S[j], qh[h], kl[j][0], kl[j][1]);
                MMA16816(S[j], ql[h], kh[j][0], kh[j][1]);
            }
            uint32_t P[8][2];
            float dA = 0.f, dB = 0.f;
#pragma unroll
            for (int j = 0; j < 8; ++j) {
                float e0 = ex2f(fmaf(mk[j][0], LOG2E, S[j][0]));
                float e1 = ex2f(fmaf(mk[j][1], LOG2E, S[j][1]));
                float e2 = ex2f(fmaf(mk[j][2], LOG2E, S[j][2]));
                float e3 = ex2f(fmaf(mk[j][3], LOG2E, S[j][3]));
                dA += e0 + e1; dB += e2 + e3;
                P[j][0] = packbf(e1, e0);
                P[j][1] = packbf(e3, e2);
            }
            denA[h] += dA; denB[h] += dB;
            const uint32_t aV = bufb + 18432u + (uint32_t)(((vrow) * 72 + h * 16 + vcol) * 2);
#pragma unroll
            for (int kc = 0; kc < 4; ++kc) {
                uint32_t Af[4] = {P[2*kc][0], P[2*kc][1], P[2*kc+1][0], P[2*kc+1][1]};
                uint32_t v0, v1, v2, v3;
                ldsm4t(v0, v1, v2, v3, aV + (uint32_t)(kc * 2304));
                MMA16816(out[h][0], Af, v0, v1);
                MMA16816(out[h][1], Af, v2, v3);
                ldsm4t(v0, v1, v2, v3, aV + 9216u + (uint32_t)(kc * 2304));
                MMA16816(out[h][0], Af, v0, v1);
                MMA16816(out[h][1], Af, v2, v3);
            }
        }
        __syncthreads();
        if (nt + 2 <= 15) {
            issue_tile(nt + 2, nt & 1);
            CP_COMMIT();
        }
    }

    // epilogue: normalize and store
    const int prA = p0 + w * 16 + (lane >> 2);
    const int prB = prA + 8;
#pragma unroll
    for (int h = 0; h < 4; ++h) {
        float dA = denA[h];
        dA += __shfl_xor_sync(0xFFFFFFFFu, dA, 1);
        dA += __shfl_xor_sync(0xFFFFFFFFu, dA, 2);
        float dB = denB[h];
        dB += __shfl_xor_sync(0xFFFFFFFFu, dB, 1);
        dB += __shfl_xor_sync(0xFFFFFFFFu, dB, 2);
        float iA = frcp(dA), iB = frcp(dB);
        int col = hg * 64 + h * 16 + (lane & 3) * 2;
        if (prA < 1000) {
            float* op = g_ATT + (size_t)(b * 1000 + prA) * 256 + col;
            *(float2*)op       = make_float2(out[h][0][0] * iA, out[h][0][1] * iA);
            *(float2*)(op + 8) = make_float2(out[h][1][0] * iA, out[h][1][1] * iA);
        }
        if (prB < 1000) {
            float* op = g_ATT + (size_t)(b * 1000 + prB) * 256 + col;
            *(float2*)op       = make_float2(out[h][0][2] * iB, out[h][0][3] * iB);
            *(float2*)(op + 8) = make_float2(out[h][1][2] * iB, out[h][1][3] * iB);
        }
    }
}

// ---------------- normalize ----------------
__global__ void norm_k(float* __restrict__ out) {
    int row = blockIdx.x;
    int c = threadIdx.x;
    if (c < 250) {
        float inv = 1.0f / g_ROWSUM[row];
        float4* p = (float4*)(out + (size_t)row * 1000);
        float4 v = p[c];
        v.x *= inv; v.y *= inv; v.z *= inv; v.w *= inv;
        p[c] = v;
    }
}

// ---------------- launch ----------------
extern "C" void kernel_launch(void* const* d_in, const int* in_sizes, int n_in,
                              void* d_out, int out_size)
{
    const float* last  = (const float*)d_in[0];
    const float* attr  = (const float*)d_in[1];
    const float* mask  = (const float*)d_in[2];
    const float* nodes = (const float*)d_in[3];
    const float* Wq    = (const float*)d_in[4];
    const float* Wk    = (const float*)d_in[5];
    const float* Wv    = (const float*)d_in[6];
    const float* Wc    = (const float*)d_in[7];
    const float* bc    = (const float*)d_in[8];
    float* out = (float*)d_out;

    void* p;
    cudaGetSymbolAddress(&p, g_KV);     float* gKV  = (float*)p;
    cudaGetSymbolAddress(&p, g_Q);      float* gQ   = (float*)p;
    cudaGetSymbolAddress(&p, g_ATT);    float* gATT = (float*)p;
    cudaGetSymbolAddress(&p, g_MH);     float* gMH  = (float*)p;
    cudaGetSymbolAddress(&p, g_WKV);    float* gWKV = (float*)p;
    cudaGetSymbolAddress(&p, g_ROWSUM); float* gRS  = (float*)p;
    cudaGetSymbolAddress(&p, g_AH);     __nv_bfloat16* gAH = (__nv_bfloat16*)p;
    cudaGetSymbolAddress(&p, g_AL);     __nv_bfloat16* gAL = (__nv_bfloat16*)p;
    cudaGetSymbolAddress(&p, g_BH);     __nv_bfloat16* gBH = (__nv_bfloat16*)p;
    cudaGetSymbolAddress(&p, g_BL);     __nv_bfloat16* gBL = (__nv_bfloat16*)p;
    cudaGetSymbolAddress(&p, g_QH);     __nv_bfloat16* gQH = (__nv_bfloat16*)p;
    cudaGetSymbolAddress(&p, g_QL);     __nv_bfloat16* gQL = (__nv_bfloat16*)p;
    cudaGetSymbolAddress(&p, g_KVH);    __nv_bfloat16* gKVH = (__nv_bfloat16*)p;
    cudaGetSymbolAddress(&p, g_KVL);    __nv_bfloat16* gKVL = (__nv_bfloat16*)p;

    cudaFuncSetAttribute(gemm3_mma, cudaFuncAttributeMaxDynamicSharedMemorySize,
                         G3_SMEM);
    cudaFuncSetAttribute(attn_mma, cudaFuncAttributeMaxDynamicSharedMemorySize,
                         AT_SMEM);

    zero_k<<<(MROWS + 255) / 256, 256>>>();
    concat_wkv<<<512, 256>>>(Wk, Wv);
    splitg_k<<<4096, 256>>>(nodes, gBH, gBL, 6, 1.0f);

    gemm_k<0><<<dim3(4, 125), 256>>>(nodes, gWKV, gKV, MROWS, 512, 512, 512,
                                     nullptr, nullptr);
    gemm_k<1><<<dim3(2, 125), 256>>>(last, Wq, gQ, MROWS, 256, 256, 256,
                                     attr, Wq + 256 * 256);

    splitg_k<<<8192, 256>>>(gKV, gKVH, gKVL, 7, 1.0f);
    splitg_k<<<4096, 256>>>(gQ, gQH, gQL, 6, 0.25f * LOG2E);

    attn_mma<<<dim3(8, 4, 16), 256, AT_SMEM>>>(mask);

    gemm_k<2><<<dim3(2, 125), 256>>>(gATT, Wc, gMH, MROWS, 256, 256, 256,
                                     bc, nullptr);

    splitg_k<<<4096, 256>>>(gMH, gAH, gAL, 6, 1.0f);
    gemm3_mma<<<dim3(8, 8, 16), 256, G3_SMEM>>>(mask, out, gRS);

    norm_k<<<MROWS, 256>>>(out);
}

// round 7
// speedup vs baseline: 1.9670x; 1.1880x over previous
#include <cuda_runtime.h>
#include <cuda_bf16.h>
#include <math.h>
#include <cstdint>

// B=16, P=1000, N=1000, E=256, H=16, D=16, HD=256
#define BSZ   16
#define PN    1000
#define MROWS (BSZ * PN)
#define LOG2E 1.4426950408889634f

typedef unsigned long long u64;

__device__ __forceinline__ float ex2f(float x) {
    float y; asm("ex2.approx.f32 %0,%1;" : "=f"(y) : "f"(x)); return y;
}
__device__ __forceinline__ float frcp(float x) {
    float y; asm("rcp.approx.f32 %0,%1;" : "=f"(y) : "f"(x)); return y;
}
__device__ __forceinline__ uint32_t smem_u32(const void* p) {
    uint32_t a;
    asm("{ .reg .u64 t; cvta.to.shared.u64 t, %1; cvt.u32.u64 %0, t; }"
        : "=r"(a) : "l"(p));
    return a;
}
__device__ __forceinline__ void ldsm4(uint32_t& r0, uint32_t& r1,
                                      uint32_t& r2, uint32_t& r3, uint32_t a) {
    asm volatile("ldmatrix.sync.aligned.m8n8.x4.shared.b16 {%0,%1,%2,%3},[%4];"
                 : "=r"(r0), "=r"(r1), "=r"(r2), "=r"(r3) : "r"(a));
}
__device__ __forceinline__ void ldsm4t(uint32_t& r0, uint32_t& r1,
                                       uint32_t& r2, uint32_t& r3, uint32_t a) {
    asm volatile("ldmatrix.sync.aligned.m8n8.x4.trans.shared.b16 {%0,%1,%2,%3},[%4];"
                 : "=r"(r0), "=r"(r1), "=r"(r2), "=r"(r3) : "r"(a));
}
__device__ __forceinline__ uint32_t packbf(float hi, float lo) {
    uint32_t r; asm("cvt.rn.bf16x2.f32 %0,%1,%2;" : "=r"(r) : "f"(hi), "f"(lo));
    return r;
}
#define MMA16816(C, A, B0, B1) \
    asm volatile("mma.sync.aligned.m16n8k16.row.col.f32.bf16.bf16.f32 " \
        "{%0,%1,%2,%3},{%4,%5,%6,%7},{%8,%9},{%0,%1,%2,%3};" \
        : "+f"((C)[0]), "+f"((C)[1]), "+f"((C)[2]), "+f"((C)[3]) \
        : "r"((A)[0]), "r"((A)[1]), "r"((A)[2]), "r"((A)[3]), \
          "r"(B0), "r"(B1))
#define CP_COMMIT() asm volatile("cp.async.commit_group;" ::: "memory")
#define CP_WAIT1()  asm volatile("cp.async.wait_group 1;" ::: "memory")
#define CP_WAIT0()  asm volatile("cp.async.wait_group 0;" ::: "memory")

// split v into hi/lo bf16 and store a pair (cols gc, gc+1)
__device__ __forceinline__ void split_store2(__nv_bfloat16* __restrict__ H,
                                             __nv_bfloat16* __restrict__ L,
                                             size_t off, float v0, float v1) {
    __nv_bfloat16 h0 = __float2bfloat16_rn(v0);
    __nv_bfloat16 h1 = __float2bfloat16_rn(v1);
    __nv_bfloat16 l0 = __float2bfloat16_rn(v0 - __bfloat162float(h0));
    __nv_bfloat16 l1 = __float2bfloat16_rn(v1 - __bfloat162float(h1));
    ushort2 hh, ll;
    hh.x = __bfloat16_as_ushort(h0); hh.y = __bfloat16_as_ushort(h1);
    ll.x = __bfloat16_as_ushort(l0); ll.y = __bfloat16_as_ushort(l1);
    *(ushort2*)(H + off) = hh;
    *(ushort2*)(L + off) = ll;
}

// ---------------- scratch ----------------
__device__ float g_ROWSUM[MROWS];
__device__ __nv_bfloat16 g_AH[16 * 1024 * 256];     // MH split (probe A)
__device__ __nv_bfloat16 g_AL[16 * 1024 * 256];
__device__ __nv_bfloat16 g_BH[16 * 1024 * 256];     // nodes split (probe B^T, KV-proj A)
__device__ __nv_bfloat16 g_BL[16 * 1024 * 256];
__device__ __nv_bfloat16 g_QH[16 * 1024 * 256];     // scaled q split
__device__ __nv_bfloat16 g_QL[16 * 1024 * 256];
__device__ __nv_bfloat16 g_KVH[16 * 1024 * 512];
__device__ __nv_bfloat16 g_KVL[16 * 1024 * 512];
__device__ __nv_bfloat16 g_LH[16 * 1024 * 256];     // last split (Q-proj A)
__device__ __nv_bfloat16 g_LL[16 * 1024 * 256];
__device__ __nv_bfloat16 g_ATH[16 * 1024 * 256];    // attention out split (Wc-proj A)
__device__ __nv_bfloat16 g_ATL[16 * 1024 * 256];
// transposed/split weights: [N rows, 256 K]
__device__ __nv_bfloat16 g_WKVTH[512 * 256];
__device__ __nv_bfloat16 g_WKVTL[512 * 256];
__device__ __nv_bfloat16 g_WQTH[256 * 256];
__device__ __nv_bfloat16 g_WQTL[256 * 256];
__device__ __nv_bfloat16 g_WCTH[256 * 256];
__device__ __nv_bfloat16 g_WCTL[256 * 256];

__global__ void zero_k() {
    int i = blockIdx.x * 256 + threadIdx.x;
    if (i < MROWS) g_ROWSUM[i] = 0.f;
}

// zero the pad rows (1000..1023) of the attention-out split arrays
__global__ void zpad_k() {
    int i = blockIdx.x * 256 + threadIdx.x;   // 16*24*256 = 98304
    if (i < 98304) {
        int z = i / 6144, rem = i % 6144;
        int r = 1000 + (rem >> 8), c = rem & 255;
        size_t off = ((size_t)z * 1024 + r) * 256 + c;
        g_ATH[off] = __ushort_as_bfloat16(0);
        g_ATL[off] = __ushort_as_bfloat16(0);
    }
}

// transpose + split all weights
__global__ void tsplit_k(const float* __restrict__ Wk, const float* __restrict__ Wv,
                         const float* __restrict__ Wq, const float* __restrict__ Wc)
{
    int idx = blockIdx.x * 256 + threadIdx.x;     // 262144 total
    float v; __nv_bfloat16 *H, *L; int off;
    if (idx < 131072) {
        int n = idx >> 8, k = idx & 255;
        v = (n < 256) ? Wk[k * 256 + n] : Wv[k * 256 + (n - 256)];
        H = g_WKVTH; L = g_WKVTL; off = idx;
    } else if (idx < 196608) {
        int i = idx - 131072;
        int n = i >> 8, k = i & 255;
        v = Wq[k * 256 + n];
        H = g_WQTH; L = g_WQTL; off = i;
    } else {
        int i = idx - 196608;
        int n = i >> 8, k = i & 255;
        v = Wc[k * 256 + n];
        H = g_WCTH; L = g_WCTL; off = i;
    }
    __nv_bfloat16 h = __float2bfloat16_rn(v);
    __nv_bfloat16 l = __float2bfloat16_rn(v - __bfloat162float(h));
    H[off] = h; L[off] = l;
}

// fp32 [16,1000,256] -> hi/lo bf16 [16,1024,256] (zero-padded rows)
__global__ void splitg_k(const float* __restrict__ src,
                         __nv_bfloat16* __restrict__ H, __nv_bfloat16* __restrict__ L)
{
    int i = blockIdx.x * 256 + threadIdx.x;
    int c4 = i & 63;
    int zr = i >> 6;
    int z = zr >> 10, r = zr & 1023;
    float4 v = make_float4(0.f, 0.f, 0.f, 0.f);
    if (r < 1000)
        v = *(const float4*)(src + ((size_t)z * 1000 + r) * 256 + c4 * 4);
    float xs[4] = {v.x, v.y, v.z, v.w};
    ushort4 hh, ll;
    unsigned short* hp = &hh.x;
    unsigned short* lp = &ll.x;
#pragma unroll
    for (int j = 0; j < 4; ++j) {
        __nv_bfloat16 h = __float2bfloat16_rn(xs[j]);
        float res = xs[j] - __bfloat162float(h);
        __nv_bfloat16 l = __float2bfloat16_rn(res);
        hp[j] = __bfloat16_as_ushort(h);
        lp[j] = __bfloat16_as_ushort(l);
    }
    *(ushort4*)(H + (size_t)zr * 256 + c4 * 4) = hh;
    *(ushort4*)(L + (size_t)zr * 256 + c4 * 4) = ll;
}

// ---------------- merged HMMA GEMM ----------------
// mainloop: C = Ah Bh^T + Ah Bl^T + Al Bh^T  (128x128 tile, K=256)
// EPI 0: split-store C                         (KV projection)
// EPI 1: C=(C+attr[row]*wql[col])*sc, split    (Q projection)
// EPI 2: C+=bias[col], split                   (Wc projection)
// EPI 3: e=exp(10*tanh(C/16)+mask), out, rowsum (probe)
#define G3_PAD   72
#define G3_TILE  (128 * G3_PAD)
#define G3_SMEM  (4 * G3_TILE * 2)

template <int EPI>
__global__ void __launch_bounds__(256, 1)
mma_gemm(const __nv_bfloat16* __restrict__ AH, const __nv_bfloat16* __restrict__ AL,
         const __nv_bfloat16* __restrict__ BH, const __nv_bfloat16* __restrict__ BL,
         __nv_bfloat16* __restrict__ CH, __nv_bfloat16* __restrict__ CL, int ldc,
         const float* __restrict__ attr, const float* __restrict__ wql,
         const float* __restrict__ bias,
         const float* __restrict__ mask, float* __restrict__ out,
         float* __restrict__ rsum)
{
    extern __shared__ __align__(16) __nv_bfloat16 smb[];
    __nv_bfloat16* Ah = smb;
    __nv_bfloat16* Al = Ah + G3_TILE;
    __nv_bfloat16* Bh = Al + G3_TILE;
    __nv_bfloat16* Bl = Bh + G3_TILE;

    const int tid = threadIdx.x;
    const int lane = tid & 31;
    const int w = tid >> 5;
    const int wm = w & 3, wn = w >> 2;
    const int z = blockIdx.z, m0 = blockIdx.y * 128, n0 = blockIdx.x * 128;

    const __nv_bfloat16* pAH = AH + ((size_t)z * 1024 + m0) * 256;
    const __nv_bfloat16* pAL = AL + ((size_t)z * 1024 + m0) * 256;
    const size_t boff = (EPI == 3) ? ((size_t)z * 1024 + n0) * 256 : (size_t)n0 * 256;
    const __nv_bfloat16* pBH = BH + boff;
    const __nv_bfloat16* pBL = BL + boff;

    float acc[2][8][4];
#pragma unroll
    for (int mi = 0; mi < 2; ++mi)
#pragma unroll
        for (int ni = 0; ni < 8; ++ni)
#pragma unroll
            for (int q = 0; q < 4; ++q) acc[mi][ni][q] = 0.f;

    const int arow = ((lane >> 3) & 1) * 8 + (lane & 7);
    const int acol = (lane >> 4) * 8;
    const int brow = (lane >> 4) * 8 + (lane & 7);
    const int bcol = ((lane >> 3) & 1) * 8;

    const uint32_t aAH = smem_u32(Ah) + (uint32_t)(((wm * 32 + arow) * G3_PAD + acol) * 2);
    const uint32_t aAL = aAH + G3_TILE * 2;
    const uint32_t aBH = smem_u32(Bh) + (uint32_t)(((wn * 64 + brow) * G3_PAD + bcol) * 2);
    const uint32_t aBL = aBH + G3_TILE * 2;

    const int lrow = tid >> 1;
    const int lhalf = (tid & 1) * 32;

#pragma unroll 1
    for (int kc = 0; kc < 4; ++kc) {
        __syncthreads();
        const int ko = kc * 64 + lhalf;
#pragma unroll
        for (int j = 0; j < 4; ++j) {
            *(uint4*)&Ah[lrow * G3_PAD + lhalf + j * 8] = *(const uint4*)(pAH + (size_t)lrow * 256 + ko + j * 8);
            *(uint4*)&Al[lrow * G3_PAD + lhalf + j * 8] = *(const uint4*)(pAL + (size_t)lrow * 256 + ko + j * 8);
            *(uint4*)&Bh[lrow * G3_PAD + lhalf + j * 8] = *(const uint4*)(pBH + (size_t)lrow * 256 + ko + j * 8);
            *(uint4*)&Bl[lrow * G3_PAD + lhalf + j * 8] = *(const uint4*)(pBL + (size_t)lrow * 256 + ko + j * 8);
        }
        __syncthreads();

#pragma unroll
        for (int ks = 0; ks < 4; ++ks) {
            const uint32_t koff = (uint32_t)(ks * 16 * 2);
            uint32_t aH0[4], aH1[4], aL0[4], aL1[4];
            ldsm4(aH0[0], aH0[1], aH0[2], aH0[3], aAH + koff);
            ldsm4(aH1[0], aH1[1], aH1[2], aH1[3], aAH + koff + 16 * G3_PAD * 2);
            ldsm4(aL0[0], aL0[1], aL0[2], aL0[3], aAL + koff);
            ldsm4(aL1[0], aL1[1], aL1[2], aL1[3], aAL + koff + 16 * G3_PAD * 2);
            uint32_t bH[8][2], bL[8][2];
#pragma unroll
            for (int pr = 0; pr < 4; ++pr) {
                uint32_t r0, r1, r2, r3;
                ldsm4(r0, r1, r2, r3, aBH + koff + (uint32_t)(pr * 16 * G3_PAD * 2));
                bH[2*pr][0] = r0; bH[2*pr][1] = r1;
                bH[2*pr+1][0] = r2; bH[2*pr+1][1] = r3;
                ldsm4(r0, r1, r2, r3, aBL + koff + (uint32_t)(pr * 16 * G3_PAD * 2));
                bL[2*pr][0] = r0; bL[2*pr][1] = r1;
                bL[2*pr+1][0] = r2; bL[2*pr+1][1] = r3;
            }
#pragma unroll
            for (int ni = 0; ni < 8; ++ni) {
                MMA16816(acc[0][ni], aH0, bH[ni][0], bH[ni][1]);
                MMA16816(acc[1][ni], aH1, bH[ni][0], bH[ni][1]);
                MMA16816(acc[0][ni], aH0, bL[ni][0], bL[ni][1]);
                MMA16816(acc[1][ni], aH1, bL[ni][0], bL[ni][1]);
                MMA16816(acc[0][ni], aL0, bH[ni][0], bH[ni][1]);
                MMA16816(acc[1][ni], aL1, bH[ni][0], bH[ni][1]);
            }
        }
    }

    if (EPI == 3) {
        const float* maskb = mask + (size_t)z * 1000000;
        float* outb = out + (size_t)z * 1000000;
#pragma unroll
        for (int mi = 0; mi < 2; ++mi) {
#pragma unroll
            for (int hrow = 0; hrow < 2; ++hrow) {
                int gr = m0 + wm * 32 + mi * 16 + (lane >> 2) + hrow * 8;
                bool rok = (gr < 1000);
                float rs = 0.f;
                const float* mrow = maskb + (size_t)gr * 1000;
                float* orow = outb + (size_t)gr * 1000;
#pragma unroll
                for (int ni = 0; ni < 8; ++ni) {
                    int gc = n0 + wn * 64 + ni * 8 + (lane & 3) * 2;
                    if (rok && gc < 1000) {
                        float v0 = acc[mi][ni][hrow * 2 + 0];
                        float v1 = acc[mi][ni][hrow * 2 + 1];
                        float2 m2 = *(const float2*)(mrow + gc);
                        float z0 = ex2f(v0 * (0.125f * LOG2E));
                        float z1 = ex2f(v1 * (0.125f * LOG2E));
                        float t0 = 10.f - 20.f * frcp(z0 + 1.f);
                        float t1 = 10.f - 20.f * frcp(z1 + 1.f);
                        float e0 = ex2f((t0 + m2.x) * LOG2E);
                        float e1 = ex2f((t1 + m2.y) * LOG2E);
                        *(float2*)(orow + gc) = make_float2(e0, e1);
                        rs += e0 + e1;
                    }
                }
                rs += __shfl_xor_sync(0xFFFFFFFFu, rs, 1);
                rs += __shfl_xor_sync(0xFFFFFFFFu, rs, 2);
                if ((lane & 3) == 0 && rok)
                    atomicAdd(&rsum[z * 1000 + gr], rs);
            }
        }
    } else {
        const float sc = 0.25f * LOG2E;
#pragma unroll
        for (int mi = 0; mi < 2; ++mi) {
#pragma unroll
            for (int hrow = 0; hrow < 2; ++hrow) {
                int grow = m0 + wm * 32 + mi * 16 + (lane >> 2) + hrow * 8;
                float av = 0.f;
                if (EPI == 1 && grow < 1000) av = attr[z * 1000 + grow];
#pragma unroll
                for (int ni = 0; ni < 8; ++ni) {
                    int gc = n0 + wn * 64 + ni * 8 + (lane & 3) * 2;
                    float v0 = acc[mi][ni][hrow * 2 + 0];
                    float v1 = acc[mi][ni][hrow * 2 + 1];
                    if (EPI == 1) {
                        v0 = (v0 + av * wql[gc]) * sc;
                        v1 = (v1 + av * wql[gc + 1]) * sc;
                    }
                    if (EPI == 2) {
                        v0 += bias[gc];
                        v1 += bias[gc + 1];
                    }
                    size_t off = ((size_t)z * 1024 + grow) * ldc + gc;
                    split_store2(CH, CL, off, v0, v1);
                }
            }
        }
    }
}

// ---------------- HMMA flash attention ----------------
#define AT_BUFSZ 71680
#define AT_SMEM  (36864 + 2 * AT_BUFSZ)

__global__ void __launch_bounds__(256, 1)
attn_mma(const float* __restrict__ mask)
{
    extern __shared__ __align__(16) char atsm[];
    const uint32_t sb = smem_u32(atsm);
    const int tid = threadIdx.x, lane = tid & 31, w = tid >> 5;
    const int p0 = blockIdx.x * 128;
    const int hg = blockIdx.y;
    const int b  = blockIdx.z;

    const __nv_bfloat16* gQHp = g_QH + ((size_t)b * 1024 + p0) * 256 + hg * 64;
    const __nv_bfloat16* gQLp = g_QL + ((size_t)b * 1024 + p0) * 256 + hg * 64;
    const float* gM = mask + (size_t)b * 1000000;

    auto cpa = [](uint32_t dst, const void* src, int n) {
        asm volatile("cp.async.cg.shared.global [%0],[%1],16,%2;"
                     :: "r"(dst), "l"(src), "r"(n) : "memory");
    };

    auto issue_tile = [&](int nt, int buf) {
        const int n0 = nt * 64;
        const uint32_t base = sb + 36864u + (uint32_t)buf * AT_BUFSZ;
#pragma unroll
        for (int i = 0; i < 2; ++i) {
            int idx = i * 256 + tid, row = idx >> 3, c = idx & 7;
            size_t srow = (size_t)(b * 1024 + n0 + row) * 512;
            uint32_t doff = (uint32_t)((row * 72 + c * 8) * 2);
            cpa(base + doff,          g_KVH + srow + hg*64 + c*8, 16);
            cpa(base + 9216 + doff,   g_KVL + srow + hg*64 + c*8, 16);
            cpa(base + 18432 + doff,  g_KVH + srow + 256 + hg*64 + c*8, 16);
            cpa(base + 27648 + doff,  g_KVL + srow + 256 + hg*64 + c*8, 16);
        }
#pragma unroll
        for (int i = 0; i < 8; ++i) {
            int idx = i * 256 + tid, row = idx >> 4, c = idx & 15;
            int gr = p0 + row, gc = n0 + c * 4;
            bool ok = (gr < 1000) && (gc < 1000);
            const float* src = ok ? (gM + (size_t)gr * 1000 + gc) : gM;
            cpa(base + 36864u + (uint32_t)((row * 68 + c * 4) * 4), src, ok ? 16 : 0);
        }
    };

#pragma unroll
    for (int i = 0; i < 4; ++i) {
        int idx = i * 256 + tid, row = idx >> 3, c = idx & 7;
        uint32_t doff = (uint32_t)((row * 72 + c * 8) * 2);
        cpa(sb + doff,          gQHp + (size_t)row * 256 + c * 8, 16);
        cpa(sb + 18432 + doff,  gQLp + (size_t)row * 256 + c * 8, 16);
    }
    issue_tile(0, 0);
    CP_COMMIT();
    issue_tile(1, 1);
    CP_COMMIT();

    const int qrow = w * 16 + (lane & 7) + ((lane >> 3) & 1) * 8;
    const int qcol = ((lane >> 4) & 1) * 8;
    const int krow = (lane & 7) + ((lane >> 4) & 1) * 8;
    const int kcol = ((lane >> 3) & 1) * 8;
    const int vrow = (lane & 7) + ((lane >> 3) & 1) * 8;
    const int vcol = ((lane >> 4) & 1) * 8;

    uint32_t qh[4][4], ql[4][4];
    float out[4][2][4];
    float denA[4], denB[4];
#pragma unroll
    for (int h = 0; h < 4; ++h) {
        denA[h] = 0.f; denB[h] = 0.f;
#pragma unroll
        for (int d = 0; d < 2; ++d)
#pragma unroll
            for (int q = 0; q < 4; ++q) out[h][d][q] = 0.f;
    }

#pragma unroll 1
    for (int nt = 0; nt < 16; ++nt) {
        if (nt < 15) { CP_WAIT1(); } else { CP_WAIT0(); }
        __syncthreads();

        const uint32_t bufb = sb + 36864u + (uint32_t)(nt & 1) * AT_BUFSZ;
        const uint32_t aM = bufb + 36864u;

        if (nt == 0) {
            const uint32_t aQ = sb + (uint32_t)((qrow * 72 + qcol) * 2);
#pragma unroll
            for (int h = 0; h < 4; ++h) {
                ldsm4(qh[h][0], qh[h][1], qh[h][2], qh[h][3], aQ + (uint32_t)(h * 32));
                ldsm4(ql[h][0], ql[h][1], ql[h][2], ql[h][3], aQ + 18432u + (uint32_t)(h * 32));
            }
        }
        if (nt == 15) {
            for (int i = tid; i < 3072; i += 256) {
                int row = i / 24, c = 40 + (i - row * 24);
                asm volatile("st.shared.f32 [%0],%1;"
                             :: "r"(aM + (uint32_t)((row * 68 + c) * 4)), "f"(-1e30f));
            }
            __syncthreads();
        }

        float mk[8][4];
        {
            uint32_t ab = aM + (uint32_t)((((w * 16) + (lane >> 2)) * 68 + (lane & 3) * 2) * 4);
#pragma unroll
            for (int j = 0; j < 8; ++j) {
                asm volatile("ld.shared.v2.f32 {%0,%1},[%2];"
                             : "=f"(mk[j][0]), "=f"(mk[j][1]) : "r"(ab + (uint32_t)(j * 32)));
                asm volatile("ld.shared.v2.f32 {%0,%1},[%2];"
                             : "=f"(mk[j][2]), "=f"(mk[j][3]) : "r"(ab + (uint32_t)(j * 32 + 2176)));
            }
        }

#pragma unroll
        for (int h = 0; h < 4; ++h) {
            const uint32_t aK = bufb + (uint32_t)(((krow) * 72 + h * 16 + kcol) * 2);
            uint32_t kh[8][2], kl[8][2];
#pragma unroll
            for (int jj = 0; jj < 4; ++jj) {
                ldsm4(kh[2*jj][0], kh[2*jj][1], kh[2*jj+1][0], kh[2*jj+1][1],
                      aK + (uint32_t)(jj * 2304));
                ldsm4(kl[2*jj][0], kl[2*jj][1], kl[2*jj+1][0], kl[2*jj+1][1],
                      aK + 9216u + (uint32_t)(jj * 2304));
            }
            float S[8][4];
#pragma unroll
            for (int j = 0; j < 8; ++j) {
                S[j][0] = 0.f; S[j][1] = 0.f; S[j][2] = 0.f; S[j][3] = 0.f;
                MMA16816(S[j], qh[h], kh[j][0], kh[j][1]);
                MMA16816(S[j], qh[h], kl[j][0], kl[j][1]);
                MMA16816(S[j], ql[h], kh[j][0], kh[j][1]);
            }
            uint32_t P[8][2];
            float dA = 0.f, dB = 0.f;
#pragma unroll
            for (int j = 0; j < 8; ++j) {
                float e0 = ex2f(fmaf(mk[j][0], LOG2E, S[j][0]));
                float e1 = ex2f(fmaf(mk[j][1], LOG2E, S[j][1]));
                float e2 = ex2f(fmaf(mk[j][2], LOG2E, S[j][2]));
                float e3 = ex2f(fmaf(mk[j][3], LOG2E, S[j][3]));
                dA += e0 + e1; dB += e2 + e3;
                P[j][0] = packbf(e1, e0);
                P[j][1] = packbf(e3, e2);
            }
            denA[h] += dA; denB[h] += dB;
            const uint32_t aV = bufb + 18432u + (uint32_t)(((vrow) * 72 + h * 16 + vcol) * 2);
#pragma unroll
            for (int kc = 0; kc < 4; ++kc) {
                uint32_t Af[4] = {P[2*kc][0], P[2*kc][1], P[2*kc+1][0], P[2*kc+1][1]};
                uint32_t v0, v1, v2, v3;
                ldsm4t(v0, v1, v2, v3, aV + (uint32_t)(kc * 2304));
                MMA16816(out[h][0], Af, v0, v1);
                MMA16816(out[h][1], Af, v2, v3);
                ldsm4t(v0, v1, v2, v3, aV + 9216u + (uint32_t)(kc * 2304));
                MMA16816(out[h][0], Af, v0, v1);
                MMA16816(out[h][1], Af, v2, v3);
            }
        }
        __syncthreads();
        if (nt + 2 <= 15) {
            issue_tile(nt + 2, nt & 1);
            CP_COMMIT();
        }
    }

    // epilogue: normalize and split-store to g_ATH/g_ATL
    const int prA = p0 + w * 16 + (lane >> 2);
    const int prB = prA + 8;
#pragma unroll
    for (int h = 0; h < 4; ++h) {
        float dA = denA[h];
        dA += __shfl_xor_sync(0xFFFFFFFFu, dA, 1);
        dA += __shfl_xor_sync(0xFFFFFFFFu, dA, 2);
        float dB = denB[h];
        dB += __shfl_xor_sync(0xFFFFFFFFu, dB, 1);
        dB += __shfl_xor_sync(0xFFFFFFFFu, dB, 2);
        float iA = frcp(dA), iB = frcp(dB);
        int col = hg * 64 + h * 16 + (lane & 3) * 2;
        if (prA < 1000) {
            size_t off = ((size_t)b * 1024 + prA) * 256 + col;
            split_store2(g_ATH, g_ATL, off,     out[h][0][0] * iA, out[h][0][1] * iA);
            split_store2(g_ATH, g_ATL, off + 8, out[h][1][0] * iA, out[h][1][1] * iA);
        }
        if (prB < 1000) {
            size_t off = ((size_t)b * 1024 + prB) * 256 + col;
            split_store2(g_ATH, g_ATL, off,     out[h][0][2] * iB, out[h][0][3] * iB);
            split_store2(g_ATH, g_ATL, off + 8, out[h][1][2] * iB, out[h][1][3] * iB);
        }
    }
}

// ---------------- normalize ----------------
__global__ void norm_k(float* __restrict__ out) {
    int row = blockIdx.x;
    int c = threadIdx.x;
    if (c < 250) {
        float inv = 1.0f / g_ROWSUM[row];
        float4* p = (float4*)(out + (size_t)row * 1000);
        float4 v = p[c];
        v.x *= inv; v.y *= inv; v.z *= inv; v.w *= inv;
        p[c] = v;
    }
}

// ---------------- launch ----------------
extern "C" void kernel_launch(void* const* d_in, const int* in_sizes, int n_in,
                              void* d_out, int out_size)
{
    const float* last  = (const float*)d_in[0];
    const float* attr  = (const float*)d_in[1];
    const float* mask  = (const float*)d_in[2];
    const float* nodes = (const float*)d_in[3];
    const float* Wq    = (const float*)d_in[4];
    const float* Wk    = (const float*)d_in[5];
    const float* Wv    = (const float*)d_in[6];
    const float* Wc    = (const float*)d_in[7];
    const float* bc    = (const float*)d_in[8];
    float* out = (float*)d_out;

    void* p;
    cudaGetSymbolAddress(&p, g_ROWSUM); float* gRS = (float*)p;
    cudaGetSymbolAddress(&p, g_AH);     __nv_bfloat16* gAH = (__nv_bfloat16*)p;
    cudaGetSymbolAddress(&p, g_AL);     __nv_bfloat16* gAL = (__nv_bfloat16*)p;
    cudaGetSymbolAddress(&p, g_BH);     __nv_bfloat16* gBH = (__nv_bfloat16*)p;
    cudaGetSymbolAddress(&p, g_BL);     __nv_bfloat16* gBL = (__nv_bfloat16*)p;
    cudaGetSymbolAddress(&p, g_QH);     __nv_bfloat16* gQH = (__nv_bfloat16*)p;
    cudaGetSymbolAddress(&p, g_QL);     __nv_bfloat16* gQL = (__nv_bfloat16*)p;
    cudaGetSymbolAddress(&p, g_KVH);    __nv_bfloat16* gKVH = (__nv_bfloat16*)p;
    cudaGetSymbolAddress(&p, g_KVL);    __nv_bfloat16* gKVL = (__nv_bfloat16*)p;
    cudaGetSymbolAddress(&p, g_LH);     __nv_bfloat16* gLH = (__nv_bfloat16*)p;
    cudaGetSymbolAddress(&p, g_LL);     __nv_bfloat16* gLL = (__nv_bfloat16*)p;
    cudaGetSymbolAddress(&p, g_ATH);    __nv_bfloat16* gATH = (__nv_bfloat16*)p;
    cudaGetSymbolAddress(&p, g_ATL);    __nv_bfloat16* gATL = (__nv_bfloat16*)p;
    cudaGetSymbolAddress(&p, g_WKVTH);  __nv_bfloat16* gWKVTH = (__nv_bfloat16*)p;
    cudaGetSymbolAddress(&p, g_WKVTL);  __nv_bfloat16* gWKVTL = (__nv_bfloat16*)p;
    cudaGetSymbolAddress(&p, g_WQTH);   __nv_bfloat16* gWQTH = (__nv_bfloat16*)p;
    cudaGetSymbolAddress(&p, g_WQTL);   __nv_bfloat16* gWQTL = (__nv_bfloat16*)p;
    cudaGetSymbolAddress(&p, g_WCTH);   __nv_bfloat16* gWCTH = (__nv_bfloat16*)p;
    cudaGetSymbolAddress(&p, g_WCTL);   __nv_bfloat16* gWCTL = (__nv_bfloat16*)p;

    cudaFuncSetAttribute(mma_gemm<0>, cudaFuncAttributeMaxDynamicSharedMemorySize, G3_SMEM);
    cudaFuncSetAttribute(mma_gemm<1>, cudaFuncAttributeMaxDynamicSharedMemorySize, G3_SMEM);
    cudaFuncSetAttribute(mma_gemm<2>, cudaFuncAttributeMaxDynamicSharedMemorySize, G3_SMEM);
    cudaFuncSetAttribute(mma_gemm<3>, cudaFuncAttributeMaxDynamicSharedMemorySize, G3_SMEM);
    cudaFuncSetAttribute(attn_mma, cudaFuncAttributeMaxDynamicSharedMemorySize, AT_SMEM);

    zero_k<<<(MROWS + 255) / 256, 256>>>();
    zpad_k<<<384, 256>>>();
    tsplit_k<<<1024, 256>>>(Wk, Wv, Wq, Wc);
    splitg_k<<<4096, 256>>>(nodes, gBH, gBL);
    splitg_k<<<4096, 256>>>(last, gLH, gLL);

    // KV projection: [16,1024,256] @ WKV^T[512,256] -> split KV
    mma_gemm<0><<<dim3(4, 8, 16), 256, G3_SMEM>>>(
        gBH, gBL, gWKVTH, gWKVTL, gKVH, gKVL, 512,
        nullptr, nullptr, nullptr, nullptr, nullptr, nullptr);
    // Q projection (+attr term, scaled): -> split Q
    mma_gemm<1><<<dim3(2, 8, 16), 256, G3_SMEM>>>(
        gLH, gLL, gWQTH, gWQTL, gQH, gQL, 256,
        attr, Wq + 256 * 256, nullptr, nullptr, nullptr, nullptr);

    attn_mma<<<dim3(8, 4, 16), 256, AT_SMEM>>>(mask);

    // Wc projection (+bias): -> split MH (probe A)
    mma_gemm<2><<<dim3(2, 8, 16), 256, G3_SMEM>>>(
        gATH, gATL, gWCTH, gWCTL, gAH, gAL, 256,
        nullptr, nullptr, bc, nullptr, nullptr, nullptr);

    // probe GEMM + clipped-softmax epilogue
    mma_gemm<3><<<dim3(8, 8, 16), 256, G3_SMEM>>>(
        gAH, gAL, gBH, gBL, nullptr, nullptr, 1000,
        nullptr, nullptr, nullptr, mask, out, gRS);

    norm_k<<<MROWS, 256>>>(out);
}

// round 8
// speedup vs baseline: 2.1802x; 1.1084x over previous
#include <cuda_runtime.h>
#include <cuda_bf16.h>
#include <math.h>
#include <cstdint>

// B=16, P=1000, N=1000, E=256, H=16, D=16, HD=256
#define BSZ   16
#define PN    1000
#define MROWS (BSZ * PN)
#define LOG2E 1.4426950408889634f

typedef unsigned long long u64;

__device__ __forceinline__ float ex2f(float x) {
    float y; asm("ex2.approx.f32 %0,%1;" : "=f"(y) : "f"(x)); return y;
}
__device__ __forceinline__ float frcp(float x) {
    float y; asm("rcp.approx.f32 %0,%1;" : "=f"(y) : "f"(x)); return y;
}
__device__ __forceinline__ uint32_t smem_u32(const void* p) {
    uint32_t a;
    asm("{ .reg .u64 t; cvta.to.shared.u64 t, %1; cvt.u32.u64 %0, t; }"
        : "=r"(a) : "l"(p));
    return a;
}
__device__ __forceinline__ void ldsm4(uint32_t& r0, uint32_t& r1,
                                      uint32_t& r2, uint32_t& r3, uint32_t a) {
    asm volatile("ldmatrix.sync.aligned.m8n8.x4.shared.b16 {%0,%1,%2,%3},[%4];"
                 : "=r"(r0), "=r"(r1), "=r"(r2), "=r"(r3) : "r"(a));
}
__device__ __forceinline__ void ldsm4t(uint32_t& r0, uint32_t& r1,
                                       uint32_t& r2, uint32_t& r3, uint32_t a) {
    asm volatile("ldmatrix.sync.aligned.m8n8.x4.trans.shared.b16 {%0,%1,%2,%3},[%4];"
                 : "=r"(r0), "=r"(r1), "=r"(r2), "=r"(r3) : "r"(a));
}
__device__ __forceinline__ uint32_t packbf(float hi, float lo) {
    uint32_t r; asm("cvt.rn.bf16x2.f32 %0,%1,%2;" : "=r"(r) : "f"(hi), "f"(lo));
    return r;
}
__device__ __forceinline__ void cpa16(uint32_t dst, const void* src) {
    asm volatile("cp.async.cg.shared.global [%0],[%1],16;"
                 :: "r"(dst), "l"(src) : "memory");
}
__device__ __forceinline__ void cpa16p(uint32_t dst, const void* src, int n) {
    asm volatile("cp.async.cg.shared.global [%0],[%1],16,%2;"
                 :: "r"(dst), "l"(src), "r"(n) : "memory");
}
#define MMA16816(C, A, B0, B1) \
    asm volatile("mma.sync.aligned.m16n8k16.row.col.f32.bf16.bf16.f32 " \
        "{%0,%1,%2,%3},{%4,%5,%6,%7},{%8,%9},{%0,%1,%2,%3};" \
        : "+f"((C)[0]), "+f"((C)[1]), "+f"((C)[2]), "+f"((C)[3]) \
        : "r"((A)[0]), "r"((A)[1]), "r"((A)[2]), "r"((A)[3]), \
          "r"(B0), "r"(B1))
#define CP_COMMIT() asm volatile("cp.async.commit_group;" ::: "memory")
#define CP_WAIT1()  asm volatile("cp.async.wait_group 1;" ::: "memory")
#define CP_WAIT0()  asm volatile("cp.async.wait_group 0;" ::: "memory")

// split v into hi/lo bf16 and store a pair (cols gc, gc+1)
__device__ __forceinline__ void split_store2(__nv_bfloat16* __restrict__ H,
                                             __nv_bfloat16* __restrict__ L,
                                             size_t off, float v0, float v1) {
    __nv_bfloat16 h0 = __float2bfloat16_rn(v0);
    __nv_bfloat16 h1 = __float2bfloat16_rn(v1);
    __nv_bfloat16 l0 = __float2bfloat16_rn(v0 - __bfloat162float(h0));
    __nv_bfloat16 l1 = __float2bfloat16_rn(v1 - __bfloat162float(h1));
    ushort2 hh, ll;
    hh.x = __bfloat16_as_ushort(h0); hh.y = __bfloat16_as_ushort(h1);
    ll.x = __bfloat16_as_ushort(l0); ll.y = __bfloat16_as_ushort(l1);
    *(ushort2*)(H + off) = hh;
    *(ushort2*)(L + off) = ll;
}

// ---------------- scratch ----------------
__device__ float g_ROWSUM[MROWS];
__device__ __nv_bfloat16 g_AH[16 * 1024 * 256];
__device__ __nv_bfloat16 g_AL[16 * 1024 * 256];
__device__ __nv_bfloat16 g_BH[16 * 1024 * 256];
__device__ __nv_bfloat16 g_BL[16 * 1024 * 256];
__device__ __nv_bfloat16 g_QH[16 * 1024 * 256];
__device__ __nv_bfloat16 g_QL[16 * 1024 * 256];
__device__ __nv_bfloat16 g_KVH[16 * 1024 * 512];
__device__ __nv_bfloat16 g_KVL[16 * 1024 * 512];
__device__ __nv_bfloat16 g_LH[16 * 1024 * 256];
__device__ __nv_bfloat16 g_LL[16 * 1024 * 256];
__device__ __nv_bfloat16 g_ATH[16 * 1024 * 256];
__device__ __nv_bfloat16 g_ATL[16 * 1024 * 256];
__device__ __nv_bfloat16 g_WKVTH[512 * 256];
__device__ __nv_bfloat16 g_WKVTL[512 * 256];
__device__ __nv_bfloat16 g_WQTH[256 * 256];
__device__ __nv_bfloat16 g_WQTL[256 * 256];
__device__ __nv_bfloat16 g_WCTH[256 * 256];
__device__ __nv_bfloat16 g_WCTL[256 * 256];

__global__ void zero_k() {
    int i = blockIdx.x * 256 + threadIdx.x;
    if (i < MROWS) g_ROWSUM[i] = 0.f;
}

__global__ void zpad_k() {
    int i = blockIdx.x * 256 + threadIdx.x;
    if (i < 98304) {
        int z = i / 6144, rem = i % 6144;
        int r = 1000 + (rem >> 8), c = rem & 255;
        size_t off = ((size_t)z * 1024 + r) * 256 + c;
        g_ATH[off] = __ushort_as_bfloat16(0);
        g_ATL[off] = __ushort_as_bfloat16(0);
    }
}

__global__ void tsplit_k(const float* __restrict__ Wk, const float* __restrict__ Wv,
                         const float* __restrict__ Wq, const float* __restrict__ Wc)
{
    int idx = blockIdx.x * 256 + threadIdx.x;
    float v; __nv_bfloat16 *H, *L; int off;
    if (idx < 131072) {
        int n = idx >> 8, k = idx & 255;
        v = (n < 256) ? Wk[k * 256 + n] : Wv[k * 256 + (n - 256)];
        H = g_WKVTH; L = g_WKVTL; off = idx;
    } else if (idx < 196608) {
        int i = idx - 131072;
        int n = i >> 8, k = i & 255;
        v = Wq[k * 256 + n];
        H = g_WQTH; L = g_WQTL; off = i;
    } else {
        int i = idx - 196608;
        int n = i >> 8, k = i & 255;
        v = Wc[k * 256 + n];
        H = g_WCTH; L = g_WCTL; off = i;
    }
    __nv_bfloat16 h = __float2bfloat16_rn(v);
    __nv_bfloat16 l = __float2bfloat16_rn(v - __bfloat162float(h));
    H[off] = h; L[off] = l;
}

__global__ void splitg_k(const float* __restrict__ src,
                         __nv_bfloat16* __restrict__ H, __nv_bfloat16* __restrict__ L)
{
    int i = blockIdx.x * 256 + threadIdx.x;
    int c4 = i & 63;
    int zr = i >> 6;
    int z = zr >> 10, r = zr & 1023;
    float4 v = make_float4(0.f, 0.f, 0.f, 0.f);
    if (r < 1000)
        v = *(const float4*)(src + ((size_t)z * 1000 + r) * 256 + c4 * 4);
    float xs[4] = {v.x, v.y, v.z, v.w};
    ushort4 hh, ll;
    unsigned short* hp = &hh.x;
    unsigned short* lp = &ll.x;
#pragma unroll
    for (int j = 0; j < 4; ++j) {
        __nv_bfloat16 h = __float2bfloat16_rn(xs[j]);
        float res = xs[j] - __bfloat162float(h);
        __nv_bfloat16 l = __float2bfloat16_rn(res);
        hp[j] = __bfloat16_as_ushort(h);
        lp[j] = __bfloat16_as_ushort(l);
    }
    *(ushort4*)(H + (size_t)zr * 256 + c4 * 4) = hh;
    *(ushort4*)(L + (size_t)zr * 256 + c4 * 4) = ll;
}

// ---------------- merged HMMA GEMM (2 CTAs/SM + cp.async loads) ----------------
#define G3_PAD   72
#define G3_TILE  (128 * G3_PAD)
#define G3_SMEM  (4 * G3_TILE * 2)

template <int EPI>
__global__ void __launch_bounds__(256, 2)
mma_gemm(const __nv_bfloat16* __restrict__ AH, const __nv_bfloat16* __restrict__ AL,
         const __nv_bfloat16* __restrict__ BH, const __nv_bfloat16* __restrict__ BL,
         __nv_bfloat16* __restrict__ CH, __nv_bfloat16* __restrict__ CL, int ldc,
         const float* __restrict__ attr, const float* __restrict__ wql,
         const float* __restrict__ bias,
         const float* __restrict__ mask, float* __restrict__ out,
         float* __restrict__ rsum)
{
    extern __shared__ __align__(16) __nv_bfloat16 smb[];
    __nv_bfloat16* Ah = smb;
    __nv_bfloat16* Al = Ah + G3_TILE;
    __nv_bfloat16* Bh = Al + G3_TILE;
    __nv_bfloat16* Bl = Bh + G3_TILE;

    const int tid = threadIdx.x;
    const int lane = tid & 31;
    const int w = tid >> 5;
    const int wm = w & 3, wn = w >> 2;
    const int z = blockIdx.z, m0 = blockIdx.y * 128, n0 = blockIdx.x * 128;

    const __nv_bfloat16* pAH = AH + ((size_t)z * 1024 + m0) * 256;
    const __nv_bfloat16* pAL = AL + ((size_t)z * 1024 + m0) * 256;
    const size_t boff = (EPI == 3) ? ((size_t)z * 1024 + n0) * 256 : (size_t)n0 * 256;
    const __nv_bfloat16* pBH = BH + boff;
    const __nv_bfloat16* pBL = BL + boff;

    float acc[2][8][4];
#pragma unroll
    for (int mi = 0; mi < 2; ++mi)
#pragma unroll
        for (int ni = 0; ni < 8; ++ni)
#pragma unroll
            for (int q = 0; q < 4; ++q) acc[mi][ni][q] = 0.f;

    const int arow = ((lane >> 3) & 1) * 8 + (lane & 7);
    const int acol = (lane >> 4) * 8;
    const int brow = (lane >> 4) * 8 + (lane & 7);
    const int bcol = ((lane >> 3) & 1) * 8;

    const uint32_t sA = smem_u32(Ah);
    const uint32_t aAH = sA + (uint32_t)(((wm * 32 + arow) * G3_PAD + acol) * 2);
    const uint32_t aAL = aAH + G3_TILE * 2;
    const uint32_t aBH = sA + 2u * G3_TILE * 2 + (uint32_t)(((wn * 64 + brow) * G3_PAD + bcol) * 2);
    const uint32_t aBL = aBH + G3_TILE * 2;

    const int lrow = tid >> 1;
    const int lhalf = (tid & 1) * 32;
    const uint32_t sdst = sA + (uint32_t)((lrow * G3_PAD + lhalf) * 2);
    const size_t gsrc = (size_t)lrow * 256;

#pragma unroll 1
    for (int kc = 0; kc < 4; ++kc) {
        __syncthreads();
        const int ko = kc * 64 + lhalf;
#pragma unroll
        for (int j = 0; j < 4; ++j) {
            cpa16(sdst + (uint32_t)(j * 16),                     pAH + gsrc + ko + j * 8);
            cpa16(sdst + (uint32_t)(G3_TILE * 2 + j * 16),       pAL + gsrc + ko + j * 8);
            cpa16(sdst + (uint32_t)(2 * G3_TILE * 2 + j * 16),   pBH + gsrc + ko + j * 8);
            cpa16(sdst + (uint32_t)(3 * G3_TILE * 2 + j * 16),   pBL + gsrc + ko + j * 8);
        }
        CP_COMMIT();
        CP_WAIT0();
        __syncthreads();

#pragma unroll
        for (int ks = 0; ks < 4; ++ks) {
            const uint32_t koff = (uint32_t)(ks * 16 * 2);
            uint32_t aH0[4], aH1[4], aL0[4], aL1[4];
            ldsm4(aH0[0], aH0[1], aH0[2], aH0[3], aAH + koff);
            ldsm4(aH1[0], aH1[1], aH1[2], aH1[3], aAH + koff + 16 * G3_PAD * 2);
            ldsm4(aL0[0], aL0[1], aL0[2], aL0[3], aAL + koff);
            ldsm4(aL1[0], aL1[1], aL1[2], aL1[3], aAL + koff + 16 * G3_PAD * 2);
            uint32_t bH[8][2], bL[8][2];
#pragma unroll
            for (int pr = 0; pr < 4; ++pr) {
                uint32_t r0, r1, r2, r3;
                ldsm4(r0, r1, r2, r3, aBH + koff + (uint32_t)(pr * 16 * G3_PAD * 2));
                bH[2*pr][0] = r0; bH[2*pr][1] = r1;
                bH[2*pr+1][0] = r2; bH[2*pr+1][1] = r3;
                ldsm4(r0, r1, r2, r3, aBL + koff + (uint32_t)(pr * 16 * G3_PAD * 2));
                bL[2*pr][0] = r0; bL[2*pr][1] = r1;
                bL[2*pr+1][0] = r2; bL[2*pr+1][1] = r3;
            }
#pragma unroll
            for (int ni = 0; ni < 8; ++ni) {
                MMA16816(acc[0][ni], aH0, bH[ni][0], bH[ni][1]);
                MMA16816(acc[1][ni], aH1, bH[ni][0], bH[ni][1]);
                MMA16816(acc[0][ni], aH0, bL[ni][0], bL[ni][1]);
                MMA16816(acc[1][ni], aH1, bL[ni][0], bL[ni][1]);
                MMA16816(acc[0][ni], aL0, bH[ni][0], bH[ni][1]);
                MMA16816(acc[1][ni], aL1, bH[ni][0], bH[ni][1]);
            }
        }
    }

    if (EPI == 3) {
        const float* maskb = mask + (size_t)z * 1000000;
        float* outb = out + (size_t)z * 1000000;
#pragma unroll
        for (int mi = 0; mi < 2; ++mi) {
#pragma unroll
            for (int hrow = 0; hrow < 2; ++hrow) {
                int gr = m0 + wm * 32 + mi * 16 + (lane >> 2) + hrow * 8;
                bool rok = (gr < 1000);
                float rs = 0.f;
                const float* mrow = maskb + (size_t)gr * 1000;
                float* orow = outb + (size_t)gr * 1000;
#pragma unroll
                for (int ni = 0; ni < 8; ++ni) {
                    int gc = n0 + wn * 64 + ni * 8 + (lane & 3) * 2;
                    if (rok && gc < 1000) {
                        float v0 = acc[mi][ni][hrow * 2 + 0];
                        float v1 = acc[mi][ni][hrow * 2 + 1];
                        float2 m2 = *(const float2*)(mrow + gc);
                        float z0 = ex2f(v0 * (0.125f * LOG2E));
                        float z1 = ex2f(v1 * (0.125f * LOG2E));
                        float t0 = 10.f - 20.f * frcp(z0 + 1.f);
                        float t1 = 10.f - 20.f * frcp(z1 + 1.f);
                        float e0 = ex2f((t0 + m2.x) * LOG2E);
                        float e1 = ex2f((t1 + m2.y) * LOG2E);
                        *(float2*)(orow + gc) = make_float2(e0, e1);
                        rs += e0 + e1;
                    }
                }
                rs += __shfl_xor_sync(0xFFFFFFFFu, rs, 1);
                rs += __shfl_xor_sync(0xFFFFFFFFu, rs, 2);
                if ((lane & 3) == 0 && rok)
                    atomicAdd(&rsum[z * 1000 + gr], rs);
            }
        }
    } else {
        const float sc = 0.25f * LOG2E;
#pragma unroll
        for (int mi = 0; mi < 2; ++mi) {
#pragma unroll
            for (int hrow = 0; hrow < 2; ++hrow) {
                int grow = m0 + wm * 32 + mi * 16 + (lane >> 2) + hrow * 8;
                float av = 0.f;
                if (EPI == 1 && grow < 1000) av = attr[z * 1000 + grow];
#pragma unroll
                for (int ni = 0; ni < 8; ++ni) {
                    int gc = n0 + wn * 64 + ni * 8 + (lane & 3) * 2;
                    float v0 = acc[mi][ni][hrow * 2 + 0];
                    float v1 = acc[mi][ni][hrow * 2 + 1];
                    if (EPI == 1) {
                        v0 = (v0 + av * wql[gc]) * sc;
                        v1 = (v1 + av * wql[gc + 1]) * sc;
                    }
                    if (EPI == 2) {
                        v0 += bias[gc];
                        v1 += bias[gc + 1];
                    }
                    size_t off = ((size_t)z * 1024 + grow) * ldc + gc;
                    split_store2(CH, CL, off, v0, v1);
                }
            }
        }
    }
}

// ---------------- HMMA flash attention (unchanged) ----------------
#define AT_BUFSZ 71680
#define AT_SMEM  (36864 + 2 * AT_BUFSZ)

__global__ void __launch_bounds__(256, 1)
attn_mma(const float* __restrict__ mask)
{
    extern __shared__ __align__(16) char atsm[];
    const uint32_t sb = smem_u32(atsm);
    const int tid = threadIdx.x, lane = tid & 31, w = tid >> 5;
    const int p0 = blockIdx.x * 128;
    const int hg = blockIdx.y;
    const int b  = blockIdx.z;

    const __nv_bfloat16* gQHp = g_QH + ((size_t)b * 1024 + p0) * 256 + hg * 64;
    const __nv_bfloat16* gQLp = g_QL + ((size_t)b * 1024 + p0) * 256 + hg * 64;
    const float* gM = mask + (size_t)b * 1000000;

    auto issue_tile = [&](int nt, int buf) {
        const int n0 = nt * 64;
        const uint32_t base = sb + 36864u + (uint32_t)buf * AT_BUFSZ;
#pragma unroll
        for (int i = 0; i < 2; ++i) {
            int idx = i * 256 + tid, row = idx >> 3, c = idx & 7;
            size_t srow = (size_t)(b * 1024 + n0 + row) * 512;
            uint32_t doff = (uint32_t)((row * 72 + c * 8) * 2);
            cpa16(base + doff,          g_KVH + srow + hg*64 + c*8);
            cpa16(base + 9216 + doff,   g_KVL + srow + hg*64 + c*8);
            cpa16(base + 18432 + doff,  g_KVH + srow + 256 + hg*64 + c*8);
            cpa16(base + 27648 + doff,  g_KVL + srow + 256 + hg*64 + c*8);
        }
#pragma unroll
        for (int i = 0; i < 8; ++i) {
            int idx = i * 256 + tid, row = idx >> 4, c = idx & 15;
            int gr = p0 + row, gc = n0 + c * 4;
            bool ok = (gr < 1000) && (gc < 1000);
            const float* src = ok ? (gM + (size_t)gr * 1000 + gc) : gM;
            cpa16p(base + 36864u + (uint32_t)((row * 68 + c * 4) * 4), src, ok ? 16 : 0);
        }
    };

#pragma unroll
    for (int i = 0; i < 4; ++i) {
        int idx = i * 256 + tid, row = idx >> 3, c = idx & 7;
        uint32_t doff = (uint32_t)((row * 72 + c * 8) * 2);
        cpa16(sb + doff,          gQHp + (size_t)row * 256 + c * 8);
        cpa16(sb + 18432 + doff,  gQLp + (size_t)row * 256 + c * 8);
    }
    issue_tile(0, 0);
    CP_COMMIT();
    issue_tile(1, 1);
    CP_COMMIT();

    const int qrow = w * 16 + (lane & 7) + ((lane >> 3) & 1) * 8;
    const int qcol = ((lane >> 4) & 1) * 8;
    const int krow = (lane & 7) + ((lane >> 4) & 1) * 8;
    const int kcol = ((lane >> 3) & 1) * 8;
    const int vrow = (lane & 7) + ((lane >> 3) & 1) * 8;
    const int vcol = ((lane >> 4) & 1) * 8;

    uint32_t qh[4][4], ql[4][4];
    float out[4][2][4];
    float denA[4], denB[4];
#pragma unroll
    for (int h = 0; h < 4; ++h) {
        denA[h] = 0.f; denB[h] = 0.f;
#pragma unroll
        for (int d = 0; d < 2; ++d)
#pragma unroll
            for (int q = 0; q < 4; ++q) out[h][d][q] = 0.f;
    }

#pragma unroll 1
    for (int nt = 0; nt < 16; ++nt) {
        if (nt < 15) { CP_WAIT1(); } else { CP_WAIT0(); }
        __syncthreads();

        const uint32_t bufb = sb + 36864u + (uint32_t)(nt & 1) * AT_BUFSZ;
        const uint32_t aM = bufb + 36864u;

        if (nt == 0) {
            const uint32_t aQ = sb + (uint32_t)((qrow * 72 + qcol) * 2);
#pragma unroll
            for (int h = 0; h < 4; ++h) {
                ldsm4(qh[h][0], qh[h][1], qh[h][2], qh[h][3], aQ + (uint32_t)(h * 32));
                ldsm4(ql[h][0], ql[h][1], ql[h][2], ql[h][3], aQ + 18432u + (uint32_t)(h * 32));
            }
        }
        if (nt == 15) {
            for (int i = tid; i < 3072; i += 256) {
                int row = i / 24, c = 40 + (i - row * 24);
                asm volatile("st.shared.f32 [%0],%1;"
                             :: "r"(aM + (uint32_t)((row * 68 + c) * 4)), "f"(-1e30f));
            }
            __syncthreads();
        }

        float mk[8][4];
        {
            uint32_t ab = aM + (uint32_t)((((w * 16) + (lane >> 2)) * 68 + (lane & 3) * 2) * 4);
#pragma unroll
            for (int j = 0; j < 8; ++j) {
                asm volatile("ld.shared.v2.f32 {%0,%1},[%2];"
                             : "=f"(mk[j][0]), "=f"(mk[j][1]) : "r"(ab + (uint32_t)(j * 32)));
                asm volatile("ld.shared.v2.f32 {%0,%1},[%2];"
                             : "=f"(mk[j][2]), "=f"(mk[j][3]) : "r"(ab + (uint32_t)(j * 32 + 2176)));
            }
        }

#pragma unroll
        for (int h = 0; h < 4; ++h) {
            const uint32_t aK = bufb + (uint32_t)(((krow) * 72 + h * 16 + kcol) * 2);
            uint32_t kh[8][2], kl[8][2];
#pragma unroll
            for (int jj = 0; jj < 4; ++jj) {
                ldsm4(kh[2*jj][0], kh[2*jj][1], kh[2*jj+1][0], kh[2*jj+1][1],
                      aK + (uint32_t)(jj * 2304));
                ldsm4(kl[2*jj][0], kl[2*jj][1], kl[2*jj+1][0], kl[2*jj+1][1],
                      aK + 9216u + (uint32_t)(jj * 2304));
            }
            float S[8][4];
#pragma unroll
            for (int j = 0; j < 8; ++j) {
                S[j][0] = 0.f; S[j][1] = 0.f; S[j][2] = 0.f; S[j][3] = 0.f;
                MMA16816(S[j], qh[h], kh[j][0], kh[j][1]);
                MMA16816(S[j], qh[h], kl[j][0], kl[j][1]);
                MMA16816(S[j], ql[h], kh[j][0], kh[j][1]);
            }
            uint32_t P[8][2];
            float dA = 0.f, dB = 0.f;
#pragma unroll
            for (int j = 0; j < 8; ++j) {
                float e0 = ex2f(fmaf(mk[j][0], LOG2E, S[j][0]));
                float e1 = ex2f(fmaf(mk[j][1], LOG2E, S[j][1]));
                float e2 = ex2f(fmaf(mk[j][2], LOG2E, S[j][2]));
                float e3 = ex2f(fmaf(mk[j][3], LOG2E, S[j][3]));
                dA += e0 + e1; dB += e2 + e3;
                P[j][0] = packbf(e1, e0);
                P[j][1] = packbf(e3, e2);
            }
            denA[h] += dA; denB[h] += dB;
            const uint32_t aV = bufb + 18432u + (uint32_t)(((vrow) * 72 + h * 16 + vcol) * 2);
#pragma unroll
            for (int kc = 0; kc < 4; ++kc) {
                uint32_t Af[4] = {P[2*kc][0], P[2*kc][1], P[2*kc+1][0], P[2*kc+1][1]};
                uint32_t v0, v1, v2, v3;
                ldsm4t(v0, v1, v2, v3, aV + (uint32_t)(kc * 2304));
                MMA16816(out[h][0], Af, v0, v1);
                MMA16816(out[h][1], Af, v2, v3);
                ldsm4t(v0, v1, v2, v3, aV + 9216u + (uint32_t)(kc * 2304));
                MMA16816(out[h][0], Af, v0, v1);
                MMA16816(out[h][1], Af, v2, v3);
            }
        }
        __syncthreads();
        if (nt + 2 <= 15) {
            issue_tile(nt + 2, nt & 1);
            CP_COMMIT();
        }
    }

    const int prA = p0 + w * 16 + (lane >> 2);
    const int prB = prA + 8;
#pragma unroll
    for (int h = 0; h < 4; ++h) {
        float dA = denA[h];
        dA += __shfl_xor_sync(0xFFFFFFFFu, dA, 1);
        dA += __shfl_xor_sync(0xFFFFFFFFu, dA, 2);
        float dB = denB[h];
        dB += __shfl_xor_sync(0xFFFFFFFFu, dB, 1);
        dB += __shfl_xor_sync(0xFFFFFFFFu, dB, 2);
        float iA = frcp(dA), iB = frcp(dB);
        int col = hg * 64 + h * 16 + (lane & 3) * 2;
        if (prA < 1000) {
            size_t off = ((size_t)b * 1024 + prA) * 256 + col;
            split_store2(g_ATH, g_ATL, off,     out[h][0][0] * iA, out[h][0][1] * iA);
            split_store2(g_ATH, g_ATL, off + 8, out[h][1][0] * iA, out[h][1][1] * iA);
        }
        if (prB < 1000) {
            size_t off = ((size_t)b * 1024 + prB) * 256 + col;
            split_store2(g_ATH, g_ATL, off,     out[h][0][2] * iB, out[h][0][3] * iB);
            split_store2(g_ATH, g_ATL, off + 8, out[h][1][2] * iB, out[h][1][3] * iB);
        }
    }
}

// ---------------- normalize ----------------
__global__ void norm_k(float* __restrict__ out) {
    int row = blockIdx.x;
    int c = threadIdx.x;
    if (c < 250) {
        float inv = 1.0f / g_ROWSUM[row];
        float4* p = (float4*)(out + (size_t)row * 1000);
        float4 v = p[c];
        v.x *= inv; v.y *= inv; v.z *= inv; v.w *= inv;
        p[c] = v;
    }
}

// ---------------- launch ----------------
extern "C" void kernel_launch(void* const* d_in, const int* in_sizes, int n_in,
                              void* d_out, int out_size)
{
    const float* last  = (const float*)d_in[0];
    const float* attr  = (const float*)d_in[1];
    const float* mask  = (const float*)d_in[2];
    const float* nodes = (const float*)d_in[3];
    const float* Wq    = (const float*)d_in[4];
    const float* Wk    = (const float*)d_in[5];
    const float* Wv    = (const float*)d_in[6];
    const float* Wc    = (const float*)d_in[7];
    const float* bc    = (const float*)d_in[8];
    float* out = (float*)d_out;

    void* p;
    cudaGetSymbolAddress(&p, g_ROWSUM); float* gRS = (float*)p;
    cudaGetSymbolAddress(&p, g_AH);     __nv_bfloat16* gAH = (__nv_bfloat16*)p;
    cudaGetSymbolAddress(&p, g_AL);     __nv_bfloat16* gAL = (__nv_bfloat16*)p;
    cudaGetSymbolAddress(&p, g_BH);     __nv_bfloat16* gBH = (__nv_bfloat16*)p;
    cudaGetSymbolAddress(&p, g_BL);     __nv_bfloat16* gBL = (__nv_bfloat16*)p;
    cudaGetSymbolAddress(&p, g_QH);     __nv_bfloat16* gQH = (__nv_bfloat16*)p;
    cudaGetSymbolAddress(&p, g_QL);     __nv_bfloat16* gQL = (__nv_bfloat16*)p;
    cudaGetSymbolAddress(&p, g_KVH);    __nv_bfloat16* gKVH = (__nv_bfloat16*)p;
    cudaGetSymbolAddress(&p, g_KVL);    __nv_bfloat16* gKVL = (__nv_bfloat16*)p;
    cudaGetSymbolAddress(&p, g_LH);     __nv_bfloat16* gLH = (__nv_bfloat16*)p;
    cudaGetSymbolAddress(&p, g_LL);     __nv_bfloat16* gLL = (__nv_bfloat16*)p;
    cudaGetSymbolAddress(&p, g_ATH);    __nv_bfloat16* gATH = (__nv_bfloat16*)p;
    cudaGetSymbolAddress(&p, g_ATL);    __nv_bfloat16* gATL = (__nv_bfloat16*)p;
    cudaGetSymbolAddress(&p, g_WKVTH);  __nv_bfloat16* gWKVTH = (__nv_bfloat16*)p;
    cudaGetSymbolAddress(&p, g_WKVTL);  __nv_bfloat16* gWKVTL = (__nv_bfloat16*)p;
    cudaGetSymbolAddress(&p, g_WQTH);   __nv_bfloat16* gWQTH = (__nv_bfloat16*)p;
    cudaGetSymbolAddress(&p, g_WQTL);   __nv_bfloat16* gWQTL = (__nv_bfloat16*)p;
    cudaGetSymbolAddress(&p, g_WCTH);   __nv_bfloat16* gWCTH = (__nv_bfloat16*)p;
    cudaGetSymbolAddress(&p, g_WCTL);   __nv_bfloat16* gWCTL = (__nv_bfloat16*)p;

    cudaFuncSetAttribute(mma_gemm<0>, cudaFuncAttributeMaxDynamicSharedMemorySize, G3_SMEM);
    cudaFuncSetAttribute(mma_gemm<1>, cudaFuncAttributeMaxDynamicSharedMemorySize, G3_SMEM);
    cudaFuncSetAttribute(mma_gemm<2>, cudaFuncAttributeMaxDynamicSharedMemorySize, G3_SMEM);
    cudaFuncSetAttribute(mma_gemm<3>, cudaFuncAttributeMaxDynamicSharedMemorySize, G3_SMEM);
    cudaFuncSetAttribute(attn_mma, cudaFuncAttributeMaxDynamicSharedMemorySize, AT_SMEM);

    zero_k<<<(MROWS + 255) / 256, 256>>>();
    zpad_k<<<384, 256>>>();
    tsplit_k<<<1024, 256>>>(Wk, Wv, Wq, Wc);
    splitg_k<<<4096, 256>>>(nodes, gBH, gBL);
    splitg_k<<<4096, 256>>>(last, gLH, gLL);

    mma_gemm<0><<<dim3(4, 8, 16), 256, G3_SMEM>>>(
        gBH, gBL, gWKVTH, gWKVTL, gKVH, gKVL, 512,
        nullptr, nullptr, nullptr, nullptr, nullptr, nullptr);
    mma_gemm<1><<<dim3(2, 8, 16), 256, G3_SMEM>>>(
        gLH, gLL, gWQTH, gWQTL, gQH, gQL, 256,
        attr, Wq + 256 * 256, nullptr, nullptr, nullptr, nullptr);

    attn_mma<<<dim3(8, 4, 16), 256, AT_SMEM>>>(mask);

    mma_gemm<2><<<dim3(2, 8, 16), 256, G3_SMEM>>>(
        gATH, gATL, gWCTH, gWCTL, gAH, gAL, 256,
        nullptr, nullptr, bc, nullptr, nullptr, nullptr);

    mma_gemm<3><<<dim3(8, 8, 16), 256, G3_SMEM>>>(
        gAH, gAL, gBH, gBL, nullptr, nullptr, 1000,
        nullptr, nullptr, nullptr, mask, out, gRS);

    norm_k<<<MROWS, 256>>>(out);
}